// round 2
// baseline (speedup 1.0000x reference)
#include <cuda_runtime.h>
#include <cuda_bf16.h>

#define Bq 4
#define Lq 4096
#define Sq 4096
#define DM 1024
#define NH 16
#define DKq 64
#define SK 40
#define NT 40
#define FSCALE 0.125f

// ---------------- scratch (static device memory, no allocs) ----------------
__device__ float    g_K[(size_t)Bq*Sq*DM];          // projected keys
__device__ float    g_V[(size_t)Bq*Sq*DM];          // projected values
__device__ float    g_W2[(size_t)Bq*NH*SK*DM];      // fused Wq^T @ K_sample
__device__ float    g_c2[Bq*NH*SK];                 // bq . K_sample
__device__ float    g_QKs[(size_t)Bq*Lq*NH*SK];     // sampled scores
__device__ float    g_Mv[Bq*NH*Lq];                 // sparsity measure M
__device__ int      g_Mtop[Bq*NH*NT];               // top indices
__device__ float    g_Qred[(size_t)Bq*NH*NT*DKq];   // gathered Q rows
__device__ float    g_ctx[(size_t)Bq*NH*NT*DKq];    // attention context
__device__ unsigned g_mask[Bq*Lq];                  // per-(b,l) head bitmask
__device__ int      g_tslot[(size_t)Bq*Lq*NH];      // t index per (b,l,h)

// ---------------- reset (graph replays must be idempotent) -----------------
__global__ void reset_mask_kernel() {
    int i = blockIdx.x * 256 + threadIdx.x;
    if (i < Bq * Lq) g_mask[i] = 0u;
}

// ---------------- SGEMM: C[M,N] = A[M,K] @ W[N,K]^T + bias[N] --------------
// 128x128 block tile, 8x8 thread tile, BK=16, 256 threads. Batched via z.
__global__ __launch_bounds__(256) void sgemm_nt(
    const float* __restrict__ A, const float* __restrict__ W,
    const float* __restrict__ bias, float* __restrict__ C,
    int M, int N, int K, size_t sA, size_t sW, size_t sB, size_t sC)
{
    A    += (size_t)blockIdx.z * sA;
    W    += (size_t)blockIdx.z * sW;
    bias += (size_t)blockIdx.z * sB;
    C    += (size_t)blockIdx.z * sC;

    __shared__ float As[16][128];
    __shared__ float Ws[16][128];

    int tid  = threadIdx.x;
    int bm   = blockIdx.y * 128, bn = blockIdx.x * 128;
    int trow = tid >> 4, tcol = tid & 15;

    float acc[8][8];
#pragma unroll
    for (int i = 0; i < 8; i++)
#pragma unroll
        for (int j = 0; j < 8; j++) acc[i][j] = 0.f;

    for (int k0 = 0; k0 < K; k0 += 16) {
#pragma unroll
        for (int ld = 0; ld < 2; ld++) {
            int v = tid + ld * 256;          // 0..511
            int r = v >> 2, c4 = (v & 3) * 4;
            float4 a = *(const float4*)(A + (size_t)(bm + r) * K + k0 + c4);
            As[c4 + 0][r] = a.x; As[c4 + 1][r] = a.y;
            As[c4 + 2][r] = a.z; As[c4 + 3][r] = a.w;
            float4 w = *(const float4*)(W + (size_t)(bn + r) * K + k0 + c4);
            Ws[c4 + 0][r] = w.x; Ws[c4 + 1][r] = w.y;
            Ws[c4 + 2][r] = w.z; Ws[c4 + 3][r] = w.w;
        }
        __syncthreads();
#pragma unroll
        for (int kk = 0; kk < 16; kk++) {
            float ar[8], wr[8];
            *(float4*)&ar[0] = *(float4*)&As[kk][trow * 8];
            *(float4*)&ar[4] = *(float4*)&As[kk][trow * 8 + 4];
            *(float4*)&wr[0] = *(float4*)&Ws[kk][tcol * 8];
            *(float4*)&wr[4] = *(float4*)&Ws[kk][tcol * 8 + 4];
#pragma unroll
            for (int i = 0; i < 8; i++)
#pragma unroll
                for (int j = 0; j < 8; j++) acc[i][j] += ar[i] * wr[j];
        }
        __syncthreads();
    }
#pragma unroll
    for (int i = 0; i < 8; i++) {
        int row = bm + trow * 8 + i;
#pragma unroll
        for (int j = 0; j < 8; j += 4) {
            int col = bn + tcol * 8 + j;
            float4 o;
            o.x = acc[i][j]     + bias[col];
            o.y = acc[i][j + 1] + bias[col + 1];
            o.z = acc[i][j + 2] + bias[col + 2];
            o.w = acc[i][j + 3] + bias[col + 3];
            *(float4*)(C + (size_t)row * N + col) = o;
        }
    }
}

// ---------------- W2[b,h*40+s,n] = sum_d Wq[h*64+d,n] * K_sample[b,h,s,d] --
__global__ __launch_bounds__(256) void build_w2_kernel(
    const float* __restrict__ Wq, const float* __restrict__ bq,
    const int* __restrict__ idx)
{
    int bh = blockIdx.x;               // b*NH + h
    int b = bh / NH, h = bh % NH;
    __shared__ float ks[SK * DKq];
    int tid = threadIdx.x;
    for (int i = tid; i < SK * DKq; i += 256) {
        int s = i / DKq, d = i % DKq;
        ks[i] = g_K[((size_t)b * Sq + idx[s]) * DM + h * DKq + d];
    }
    __syncthreads();
    if (tid < SK) {
        float c = 0.f;
#pragma unroll
        for (int d = 0; d < DKq; d++) c += bq[h * DKq + d] * ks[tid * DKq + d];
        g_c2[bh * SK + tid] = c;
    }
    for (int p = 0; p < DM / 256; p++) {
        int n = p * 256 + tid;
        float acc[SK];
#pragma unroll
        for (int s = 0; s < SK; s++) acc[s] = 0.f;
        for (int d = 0; d < DKq; d++) {
            float w = Wq[(size_t)(h * DKq + d) * DM + n];
#pragma unroll
            for (int s = 0; s < SK; s++) acc[s] += w * ks[s * DKq + d];
        }
#pragma unroll
        for (int s = 0; s < SK; s++)
            g_W2[((size_t)bh * SK + s) * DM + n] = acc[s];
    }
}

// ---------------- M[b,h,l] = max_s QKs - mean_s QKs  (warp per row) --------
__global__ __launch_bounds__(256) void reduce_m_kernel() {
    int wg   = blockIdx.x * 8 + (threadIdx.x >> 5);   // [0, B*L*NH)
    int lane = threadIdx.x & 31;
    int h  = wg % NH;
    int bl = wg / NH;                                  // b*L + l
    int b  = bl / Lq, l = bl % Lq;
    const float* p = g_QKs + (size_t)bl * (NH * SK) + h * SK;
    float v0 = p[lane];
    float v1 = (lane < SK - 32) ? p[32 + lane] : -3.0e38f;
    float mx = fmaxf(v0, v1);
    float sm = v0 + ((lane < SK - 32) ? p[32 + lane] : 0.f);
#pragma unroll
    for (int o = 16; o; o >>= 1) {
        mx = fmaxf(mx, __shfl_xor_sync(~0u, mx, o));
        sm += __shfl_xor_sync(~0u, sm, o);
    }
    if (lane == 0)
        g_Mv[((size_t)b * NH + h) * Lq + l] = mx - sm * (1.0f / SK);
}

// ---------------- top-40 per (b,h); writes Mtop + inverse map --------------
__global__ __launch_bounds__(256) void topk_kernel() {
    int bh = blockIdx.x;
    int b = bh / NH, h = bh % NH;
    __shared__ float vals[Lq];
    __shared__ float rv[256];
    __shared__ int   ri[256];
    int tid = threadIdx.x;
    for (int i = tid; i < Lq; i += 256) vals[i] = g_Mv[(size_t)bh * Lq + i];
    __syncthreads();
    for (int t = 0; t < NT; t++) {
        float best = -3.4e38f; int bi = 0;
        for (int i = tid; i < Lq; i += 256) {
            float v = vals[i];
            if (v > best) { best = v; bi = i; }
        }
        rv[tid] = best; ri[tid] = bi;
        __syncthreads();
        for (int s = 128; s > 0; s >>= 1) {
            if (tid < s) {
                float ov = rv[tid + s]; int oi = ri[tid + s];
                if (ov > rv[tid] || (ov == rv[tid] && oi < ri[tid])) {
                    rv[tid] = ov; ri[tid] = oi;
                }
            }
            __syncthreads();
        }
        if (tid == 0) {
            int li = ri[0];
            g_Mtop[bh * NT + t] = li;
            g_tslot[((size_t)b * Lq + li) * NH + h] = t;
            atomicOr(&g_mask[b * Lq + li], 1u << h);
            vals[li] = -3.4e38f;
        }
        __syncthreads();
    }
}

// ---------------- Q_red[b,h,t,:] = queries[b,l]@Wq_h^T + bq_h --------------
__global__ __launch_bounds__(256) void qred_kernel(
    const float* __restrict__ queries, const float* __restrict__ Wq,
    const float* __restrict__ bq)
{
    int gb = blockIdx.x;              // (b*NH+h)*NT + t
    int t = gb % NT; int bh = gb / NT;
    int h = bh % NH; int b = bh / NH;
    int l = g_Mtop[bh * NT + t];
    __shared__ float qrow[DM];
    int tid = threadIdx.x;
    ((float4*)qrow)[tid] = ((const float4*)(queries + ((size_t)b * Lq + l) * DM))[tid];
    __syncthreads();
    int warp = tid >> 5, lane = tid & 31;
#pragma unroll
    for (int p = 0; p < 8; p++) {
        int d = p * 8 + warp;
        const float* wrow = Wq + (size_t)(h * DKq + d) * DM;
        float s = 0.f;
#pragma unroll
        for (int it = 0; it < 8; it++) {
            float4 w4 = *(const float4*)(wrow + it * 128 + lane * 4);
            float4 q4 = *(const float4*)(qrow + it * 128 + lane * 4);
            s += w4.x * q4.x + w4.y * q4.y + w4.z * q4.z + w4.w * q4.w;
        }
#pragma unroll
        for (int o = 16; o; o >>= 1) s += __shfl_xor_sync(~0u, s, o);
        if (lane == 0) g_Qred[(size_t)gb * DKq + d] = s + bq[h * DKq + d];
    }
}

// ---------------- flash attention: 40 queries vs S=4096 keys per (b,h) -----
#define KSP (DKq + 4)   // padded K-tile stride (16B-aligned, conflict-free)
__global__ __launch_bounds__(256) void attn_kernel() {
    int bh = blockIdx.x;
    int b = bh / NH, h = bh % NH;
    __shared__ float Qs[NT * DKq];
    __shared__ float Ks[32 * KSP];
    __shared__ float Vs[32 * DKq];
    __shared__ float Ps[NT * 32];
    int tid = threadIdx.x, warp = tid >> 5, lane = tid & 31;

    for (int i = tid; i < NT * DKq / 4; i += 256)
        ((float4*)Qs)[i] = ((const float4*)(g_Qred + (size_t)bh * NT * DKq))[i];

    float acc0[5], acc1[5], mrow[5], lrow[5];
#pragma unroll
    for (int r = 0; r < 5; r++) { acc0[r] = 0.f; acc1[r] = 0.f; mrow[r] = -3.0e38f; lrow[r] = 0.f; }

    for (int s0 = 0; s0 < Sq; s0 += 32) {
        __syncthreads();
#pragma unroll
        for (int ld = 0; ld < 2; ld++) {
            int v = tid + ld * 256;
            int r = v >> 4, c4 = (v & 15) * 4;
            size_t gbase = ((size_t)b * Sq + s0 + r) * DM + h * DKq + c4;
            float4 kf = *(const float4*)(g_K + gbase);
            Ks[r * KSP + c4 + 0] = kf.x; Ks[r * KSP + c4 + 1] = kf.y;
            Ks[r * KSP + c4 + 2] = kf.z; Ks[r * KSP + c4 + 3] = kf.w;
            float4 vf = *(const float4*)(g_V + gbase);
            *(float4*)&Vs[r * DKq + c4] = vf;
        }
        __syncthreads();

        float score[5];
#pragma unroll
        for (int r = 0; r < 5; r++) score[r] = 0.f;
#pragma unroll
        for (int d4 = 0; d4 < DKq; d4 += 4) {
            float4 k4 = *(float4*)&Ks[lane * KSP + d4];
#pragma unroll
            for (int r = 0; r < 5; r++) {
                float4 q4 = *(float4*)&Qs[(warp * 5 + r) * DKq + d4];
                score[r] += q4.x * k4.x + q4.y * k4.y + q4.z * k4.z + q4.w * k4.w;
            }
        }
#pragma unroll
        for (int r = 0; r < 5; r++) {
            float sc = score[r] * FSCALE;
            float mx = sc;
#pragma unroll
            for (int o = 16; o; o >>= 1) mx = fmaxf(mx, __shfl_xor_sync(~0u, mx, o));
            float mnew  = fmaxf(mrow[r], mx);
            float p     = expf(sc - mnew);
            float alpha = expf(mrow[r] - mnew);
            float psum  = p;
#pragma unroll
            for (int o = 16; o; o >>= 1) psum += __shfl_xor_sync(~0u, psum, o);
            lrow[r] = lrow[r] * alpha + psum;
            mrow[r] = mnew;
            acc0[r] *= alpha; acc1[r] *= alpha;
            Ps[(warp * 5 + r) * 32 + lane] = p;
        }
        __syncwarp();
#pragma unroll 4
        for (int ss = 0; ss < 32; ss++) {
            float2 v2 = *(float2*)&Vs[ss * DKq + lane * 2];
#pragma unroll
            for (int r = 0; r < 5; r++) {
                float pr = Ps[(warp * 5 + r) * 32 + ss];
                acc0[r] += pr * v2.x; acc1[r] += pr * v2.y;
            }
        }
        __syncwarp();
    }
#pragma unroll
    for (int r = 0; r < 5; r++) {
        float inv = 1.0f / lrow[r];
        float2 o2; o2.x = acc0[r] * inv; o2.y = acc1[r] * inv;
        *(float2*)(g_ctx + ((size_t)bh * NT + warp * 5 + r) * DKq + lane * 2) = o2;
    }
}

// ---------------- sparse output projection: out = scatter(ctx) @ Wo^T + bo --
__global__ __launch_bounds__(256) void out_kernel(
    const float* __restrict__ Wo, const float* __restrict__ bo,
    float* __restrict__ out)
{
    int row = blockIdx.x;            // b*L + l
    int b = row / Lq;
    int tid = threadIdx.x, warp = tid >> 5, lane = tid & 31;
    unsigned msk = g_mask[row];
    __shared__ float osm[DM];
    __shared__ float csm[DKq];

    ((float4*)osm)[tid] = ((const float4*)bo)[tid];
    __syncthreads();

    if (msk) {
        for (int h = 0; h < NH; h++) {
            if (!((msk >> h) & 1u)) continue;
            int t = g_tslot[(size_t)row * NH + h];
            if (tid < DKq / 4)
                ((float4*)csm)[tid] =
                    ((const float4*)(g_ctx + ((size_t)(b * NH + h) * NT + t) * DKq))[tid];
            __syncthreads();
            float c0 = csm[lane], c1 = csm[32 + lane];
            for (int j = 0; j < 128; j++) {
                int m = warp * 128 + j;
                const float* wrow = Wo + (size_t)m * DM + h * DKq;
                float s = wrow[lane] * c0 + wrow[32 + lane] * c1;
#pragma unroll
                for (int o = 16; o; o >>= 1) s += __shfl_xor_sync(~0u, s, o);
                if (lane == 0) osm[m] += s;
            }
            __syncthreads();
        }
    }
    ((float4*)(out + (size_t)row * DM))[tid] = ((float4*)osm)[tid];
}

// ---------------- launch -----------------------------------------------------
extern "C" void kernel_launch(void* const* d_in, const int* in_sizes, int n_in,
                              void* d_out, int out_size)
{
    const float* queries = (const float*)d_in[0];
    const float* keys    = (const float*)d_in[1];
    const float* values  = (const float*)d_in[2];
    const float* Wq      = (const float*)d_in[3];
    const float* bq      = (const float*)d_in[4];
    const float* Wk      = (const float*)d_in[5];
    const float* bk      = (const float*)d_in[6];
    const float* Wv      = (const float*)d_in[7];
    const float* bv      = (const float*)d_in[8];
    const float* Wo      = (const float*)d_in[9];
    const float* bo      = (const float*)d_in[10];
    const int*   idx     = (const int*)d_in[11];
    float* out = (float*)d_out;

    void *pK, *pV, *pW2, *pc2, *pQKs;
    cudaGetSymbolAddress(&pK,  g_K);
    cudaGetSymbolAddress(&pV,  g_V);
    cudaGetSymbolAddress(&pW2, g_W2);
    cudaGetSymbolAddress(&pc2, g_c2);
    cudaGetSymbolAddress(&pQKs, g_QKs);

    reset_mask_kernel<<<(Bq * Lq + 255) / 256, 256>>>();

    // K = keys @ Wk^T + bk ; V = values @ Wv^T + bv   (M=16384,N=1024,K=1024)
    {
        dim3 grid(DM / 128, (Bq * Sq) / 128, 1);
        sgemm_nt<<<grid, 256>>>(keys,   Wk, bk, (float*)pK, Bq * Sq, DM, DM, 0, 0, 0, 0);
        sgemm_nt<<<grid, 256>>>(values, Wv, bv, (float*)pV, Bq * Sq, DM, DM, 0, 0, 0, 0);
    }

    build_w2_kernel<<<Bq * NH, 256>>>(Wq, bq, idx);

    // QKs[b] = queries[b] @ W2[b]^T + c2[b]   (M=4096,N=640,K=1024), batched over b
    {
        dim3 grid((NH * SK) / 128, Lq / 128, Bq);
        sgemm_nt<<<grid, 256>>>(queries, (const float*)pW2, (const float*)pc2,
                                (float*)pQKs, Lq, NH * SK, DM,
                                (size_t)Lq * DM, (size_t)NH * SK * DM,
                                (size_t)NH * SK, (size_t)Lq * NH * SK);
    }

    reduce_m_kernel<<<(Bq * Lq * NH) / 8, 256>>>();
    topk_kernel<<<Bq * NH, 256>>>();
    qred_kernel<<<Bq * NH * NT, 256>>>(queries, Wq, bq);
    attn_kernel<<<Bq * NH, 256>>>();
    out_kernel<<<Bq * Lq, 256>>>(Wo, bo, out);
}

// round 4
// speedup vs baseline: 1.0009x; 1.0009x over previous
#include <cuda_runtime.h>
#include <cuda_bf16.h>

#define Bq 4
#define Lq 4096
#define Sq 4096
#define DM 1024
#define NH 16
#define DKq 64
#define SK 40
#define NT 40
#define FSCALE 0.125f

// ---------------- scratch (static device memory, no allocs) ----------------
__device__ float    g_K[(size_t)Bq*Sq*DM];          // projected keys
__device__ float    g_V[(size_t)Bq*Sq*DM];          // projected values
__device__ float    g_W2[(size_t)Bq*NH*SK*DM];      // fused Wq^T @ K_sample
__device__ float    g_c2[Bq*NH*SK];                 // bq . K_sample
__device__ float    g_QKs[(size_t)Bq*Lq*NH*SK];     // sampled scores
__device__ float    g_Mv[Bq*NH*Lq];                 // sparsity measure M
__device__ int      g_Mtop[Bq*NH*NT];               // top indices
__device__ float    g_Qred[(size_t)Bq*NH*NT*DKq];   // gathered Q rows
__device__ float    g_ctx[(size_t)Bq*NH*NT*DKq];    // attention context
__device__ unsigned g_mask[Bq*Lq];                  // per-(b,l) head bitmask
__device__ int      g_tslot[(size_t)Bq*Lq*NH];      // t index per (b,l,h)

// ---------------- reset (graph replays must be idempotent) -----------------
__global__ void reset_mask_kernel() {
    int i = blockIdx.x * 256 + threadIdx.x;
    if (i < Bq * Lq) g_mask[i] = 0u;
}

// ---------------- SGEMM: C[M,N] = A[M,K] @ W[N,K]^T + bias[N] --------------
// 128x128 block tile, 8x8 thread tile, BK=16, 256 threads. Batched via z.
__global__ __launch_bounds__(256) void sgemm_nt(
    const float* __restrict__ A, const float* __restrict__ W,
    const float* __restrict__ bias, float* __restrict__ C,
    int M, int N, int K, size_t sA, size_t sW, size_t sB, size_t sC)
{
    A    += (size_t)blockIdx.z * sA;
    W    += (size_t)blockIdx.z * sW;
    bias += (size_t)blockIdx.z * sB;
    C    += (size_t)blockIdx.z * sC;

    __shared__ float As[16][128];
    __shared__ float Ws[16][128];

    int tid  = threadIdx.x;
    int bm   = blockIdx.y * 128, bn = blockIdx.x * 128;
    int trow = tid >> 4, tcol = tid & 15;

    float acc[8][8];
#pragma unroll
    for (int i = 0; i < 8; i++)
#pragma unroll
        for (int j = 0; j < 8; j++) acc[i][j] = 0.f;

    for (int k0 = 0; k0 < K; k0 += 16) {
#pragma unroll
        for (int ld = 0; ld < 2; ld++) {
            int v = tid + ld * 256;          // 0..511
            int r = v >> 2, c4 = (v & 3) * 4;
            float4 a = *(const float4*)(A + (size_t)(bm + r) * K + k0 + c4);
            As[c4 + 0][r] = a.x; As[c4 + 1][r] = a.y;
            As[c4 + 2][r] = a.z; As[c4 + 3][r] = a.w;
            float4 w = *(const float4*)(W + (size_t)(bn + r) * K + k0 + c4);
            Ws[c4 + 0][r] = w.x; Ws[c4 + 1][r] = w.y;
            Ws[c4 + 2][r] = w.z; Ws[c4 + 3][r] = w.w;
        }
        __syncthreads();
#pragma unroll
        for (int kk = 0; kk < 16; kk++) {
            float ar[8], wr[8];
            *(float4*)&ar[0] = *(float4*)&As[kk][trow * 8];
            *(float4*)&ar[4] = *(float4*)&As[kk][trow * 8 + 4];
            *(float4*)&wr[0] = *(float4*)&Ws[kk][tcol * 8];
            *(float4*)&wr[4] = *(float4*)&Ws[kk][tcol * 8 + 4];
#pragma unroll
            for (int i = 0; i < 8; i++)
#pragma unroll
                for (int j = 0; j < 8; j++) acc[i][j] += ar[i] * wr[j];
        }
        __syncthreads();
    }
#pragma unroll
    for (int i = 0; i < 8; i++) {
        int row = bm + trow * 8 + i;
#pragma unroll
        for (int j = 0; j < 8; j += 4) {
            int col = bn + tcol * 8 + j;
            float4 o;
            o.x = acc[i][j]     + bias[col];
            o.y = acc[i][j + 1] + bias[col + 1];
            o.z = acc[i][j + 2] + bias[col + 2];
            o.w = acc[i][j + 3] + bias[col + 3];
            *(float4*)(C + (size_t)row * N + col) = o;
        }
    }
}

// ---------------- W2[b,h*40+s,n] = sum_d Wq[h*64+d,n] * K_sample[b,h,s,d] --
__global__ __launch_bounds__(256) void build_w2_kernel(
    const float* __restrict__ Wq, const float* __restrict__ bq,
    const int* __restrict__ idx)
{
    int bh = blockIdx.x;               // b*NH + h
    int b = bh / NH, h = bh % NH;
    __shared__ float ks[SK * DKq];
    int tid = threadIdx.x;
    for (int i = tid; i < SK * DKq; i += 256) {
        int s = i / DKq, d = i % DKq;
        ks[i] = g_K[((size_t)b * Sq + idx[s]) * DM + h * DKq + d];
    }
    __syncthreads();
    if (tid < SK) {
        float c = 0.f;
#pragma unroll
        for (int d = 0; d < DKq; d++) c += bq[h * DKq + d] * ks[tid * DKq + d];
        g_c2[bh * SK + tid] = c;
    }
    for (int p = 0; p < DM / 256; p++) {
        int n = p * 256 + tid;
        float acc[SK];
#pragma unroll
        for (int s = 0; s < SK; s++) acc[s] = 0.f;
        for (int d = 0; d < DKq; d++) {
            float w = Wq[(size_t)(h * DKq + d) * DM + n];
#pragma unroll
            for (int s = 0; s < SK; s++) acc[s] += w * ks[s * DKq + d];
        }
#pragma unroll
        for (int s = 0; s < SK; s++)
            g_W2[((size_t)bh * SK + s) * DM + n] = acc[s];
    }
}

// ---------------- M[b,h,l] = max_s QKs - mean_s QKs  (warp per row) --------
__global__ __launch_bounds__(256) void reduce_m_kernel() {
    int wg   = blockIdx.x * 8 + (threadIdx.x >> 5);   // [0, B*L*NH)
    int lane = threadIdx.x & 31;
    int h  = wg % NH;
    int bl = wg / NH;                                  // b*L + l
    int b  = bl / Lq, l = bl % Lq;
    const float* p = g_QKs + (size_t)bl * (NH * SK) + h * SK;
    float v0 = p[lane];
    float v1 = (lane < SK - 32) ? p[32 + lane] : -3.0e38f;
    float mx = fmaxf(v0, v1);
    float sm = v0 + ((lane < SK - 32) ? p[32 + lane] : 0.f);
#pragma unroll
    for (int o = 16; o; o >>= 1) {
        mx = fmaxf(mx, __shfl_xor_sync(~0u, mx, o));
        sm += __shfl_xor_sync(~0u, sm, o);
    }
    if (lane == 0)
        g_Mv[((size_t)b * NH + h) * Lq + l] = mx - sm * (1.0f / SK);
}

// ---------------- top-40 per (b,h); writes Mtop + inverse map --------------
__global__ __launch_bounds__(256) void topk_kernel() {
    int bh = blockIdx.x;
    int b = bh / NH, h = bh % NH;
    __shared__ float vals[Lq];
    __shared__ float rv[256];
    __shared__ int   ri[256];
    int tid = threadIdx.x;
    for (int i = tid; i < Lq; i += 256) vals[i] = g_Mv[(size_t)bh * Lq + i];
    __syncthreads();
    for (int t = 0; t < NT; t++) {
        float best = -3.4e38f; int bi = 0;
        for (int i = tid; i < Lq; i += 256) {
            float v = vals[i];
            if (v > best) { best = v; bi = i; }
        }
        rv[tid] = best; ri[tid] = bi;
        __syncthreads();
        for (int s = 128; s > 0; s >>= 1) {
            if (tid < s) {
                float ov = rv[tid + s]; int oi = ri[tid + s];
                if (ov > rv[tid] || (ov == rv[tid] && oi < ri[tid])) {
                    rv[tid] = ov; ri[tid] = oi;
                }
            }
            __syncthreads();
        }
        if (tid == 0) {
            int li = ri[0];
            g_Mtop[bh * NT + t] = li;
            g_tslot[((size_t)b * Lq + li) * NH + h] = t;
            atomicOr(&g_mask[b * Lq + li], 1u << h);
            vals[li] = -3.4e38f;
        }
        __syncthreads();
    }
}

// ---------------- Q_red[b,h,t,:] = queries[b,l]@Wq_h^T + bq_h --------------
__global__ __launch_bounds__(256) void qred_kernel(
    const float* __restrict__ queries, const float* __restrict__ Wq,
    const float* __restrict__ bq)
{
    int gb = blockIdx.x;              // (b*NH+h)*NT + t
    int t = gb % NT; int bh = gb / NT;
    int h = bh % NH; int b = bh / NH;
    int l = g_Mtop[bh * NT + t];
    __shared__ float qrow[DM];
    int tid = threadIdx.x;
    ((float4*)qrow)[tid] = ((const float4*)(queries + ((size_t)b * Lq + l) * DM))[tid];
    __syncthreads();
    int warp = tid >> 5, lane = tid & 31;
#pragma unroll
    for (int p = 0; p < 8; p++) {
        int d = p * 8 + warp;
        const float* wrow = Wq + (size_t)(h * DKq + d) * DM;
        float s = 0.f;
#pragma unroll
        for (int it = 0; it < 8; it++) {
            float4 w4 = *(const float4*)(wrow + it * 128 + lane * 4);
            float4 q4 = *(const float4*)(qrow + it * 128 + lane * 4);
            s += w4.x * q4.x + w4.y * q4.y + w4.z * q4.z + w4.w * q4.w;
        }
#pragma unroll
        for (int o = 16; o; o >>= 1) s += __shfl_xor_sync(~0u, s, o);
        if (lane == 0) g_Qred[(size_t)gb * DKq + d] = s + bq[h * DKq + d];
    }
}

// ---------------- flash attention: 40 queries vs S=4096 keys per (b,h) -----
#define KSP (DKq + 4)   // padded K-tile stride (16B-aligned, conflict-free)
__global__ __launch_bounds__(256) void attn_kernel() {
    int bh = blockIdx.x;
    int b = bh / NH, h = bh % NH;
    __shared__ float Qs[NT * DKq];
    __shared__ float Ks[32 * KSP];
    __shared__ float Vs[32 * DKq];
    __shared__ float Ps[NT * 32];
    int tid = threadIdx.x, warp = tid >> 5, lane = tid & 31;

    for (int i = tid; i < NT * DKq / 4; i += 256)
        ((float4*)Qs)[i] = ((const float4*)(g_Qred + (size_t)bh * NT * DKq))[i];

    float acc0[5], acc1[5], mrow[5], lrow[5];
#pragma unroll
    for (int r = 0; r < 5; r++) { acc0[r] = 0.f; acc1[r] = 0.f; mrow[r] = -3.0e38f; lrow[r] = 0.f; }

    for (int s0 = 0; s0 < Sq; s0 += 32) {
        __syncthreads();
#pragma unroll
        for (int ld = 0; ld < 2; ld++) {
            int v = tid + ld * 256;
            int r = v >> 4, c4 = (v & 15) * 4;
            size_t gbase = ((size_t)b * Sq + s0 + r) * DM + h * DKq + c4;
            float4 kf = *(const float4*)(g_K + gbase);
            Ks[r * KSP + c4 + 0] = kf.x; Ks[r * KSP + c4 + 1] = kf.y;
            Ks[r * KSP + c4 + 2] = kf.z; Ks[r * KSP + c4 + 3] = kf.w;
            float4 vf = *(const float4*)(g_V + gbase);
            *(float4*)&Vs[r * DKq + c4] = vf;
        }
        __syncthreads();

        float score[5];
#pragma unroll
        for (int r = 0; r < 5; r++) score[r] = 0.f;
#pragma unroll
        for (int d4 = 0; d4 < DKq; d4 += 4) {
            float4 k4 = *(float4*)&Ks[lane * KSP + d4];
#pragma unroll
            for (int r = 0; r < 5; r++) {
                float4 q4 = *(float4*)&Qs[(warp * 5 + r) * DKq + d4];
                score[r] += q4.x * k4.x + q4.y * k4.y + q4.z * k4.z + q4.w * k4.w;
            }
        }
#pragma unroll
        for (int r = 0; r < 5; r++) {
            float sc = score[r] * FSCALE;
            float mx = sc;
#pragma unroll
            for (int o = 16; o; o >>= 1) mx = fmaxf(mx, __shfl_xor_sync(~0u, mx, o));
            float mnew  = fmaxf(mrow[r], mx);
            float p     = expf(sc - mnew);
            float alpha = expf(mrow[r] - mnew);
            float psum  = p;
#pragma unroll
            for (int o = 16; o; o >>= 1) psum += __shfl_xor_sync(~0u, psum, o);
            lrow[r] = lrow[r] * alpha + psum;
            mrow[r] = mnew;
            acc0[r] *= alpha; acc1[r] *= alpha;
            Ps[(warp * 5 + r) * 32 + lane] = p;
        }
        __syncwarp();
#pragma unroll 4
        for (int ss = 0; ss < 32; ss++) {
            float2 v2 = *(float2*)&Vs[ss * DKq + lane * 2];
#pragma unroll
            for (int r = 0; r < 5; r++) {
                float pr = Ps[(warp * 5 + r) * 32 + ss];
                acc0[r] += pr * v2.x; acc1[r] += pr * v2.y;
            }
        }
        __syncwarp();
    }
#pragma unroll
    for (int r = 0; r < 5; r++) {
        float inv = 1.0f / lrow[r];
        float2 o2; o2.x = acc0[r] * inv; o2.y = acc1[r] * inv;
        *(float2*)(g_ctx + ((size_t)bh * NT + warp * 5 + r) * DKq + lane * 2) = o2;
    }
}

// ---------------- sparse output projection: out = scatter(ctx) @ Wo^T + bo --
__global__ __launch_bounds__(256) void out_kernel(
    const float* __restrict__ Wo, const float* __restrict__ bo,
    float* __restrict__ out)
{
    int row = blockIdx.x;            // b*L + l
    int b = row / Lq;
    int tid = threadIdx.x, warp = tid >> 5, lane = tid & 31;
    unsigned msk = g_mask[row];
    __shared__ float osm[DM];
    __shared__ float csm[DKq];

    ((float4*)osm)[tid] = ((const float4*)bo)[tid];
    __syncthreads();

    if (msk) {
        for (int h = 0; h < NH; h++) {
            if (!((msk >> h) & 1u)) continue;
            int t = g_tslot[(size_t)row * NH + h];
            if (tid < DKq / 4)
                ((float4*)csm)[tid] =
                    ((const float4*)(g_ctx + ((size_t)(b * NH + h) * NT + t) * DKq))[tid];
            __syncthreads();
            float c0 = csm[lane], c1 = csm[32 + lane];
            for (int j = 0; j < 128; j++) {
                int m = warp * 128 + j;
                const float* wrow = Wo + (size_t)m * DM + h * DKq;
                float s = wrow[lane] * c0 + wrow[32 + lane] * c1;
#pragma unroll
                for (int o = 16; o; o >>= 1) s += __shfl_xor_sync(~0u, s, o);
                if (lane == 0) osm[m] += s;
            }
            __syncthreads();
        }
    }
    ((float4*)(out + (size_t)row * DM))[tid] = ((float4*)osm)[tid];
}

// ---------------- launch -----------------------------------------------------
extern "C" void kernel_launch(void* const* d_in, const int* in_sizes, int n_in,
                              void* d_out, int out_size)
{
    const float* queries = (const float*)d_in[0];
    const float* keys    = (const float*)d_in[1];
    const float* values  = (const float*)d_in[2];
    const float* Wq      = (const float*)d_in[3];
    const float* bq      = (const float*)d_in[4];
    const float* Wk      = (const float*)d_in[5];
    const float* bk      = (const float*)d_in[6];
    const float* Wv      = (const float*)d_in[7];
    const float* bv      = (const float*)d_in[8];
    const float* Wo      = (const float*)d_in[9];
    const float* bo      = (const float*)d_in[10];
    const int*   idx     = (const int*)d_in[11];
    float* out = (float*)d_out;

    void *pK, *pV, *pW2, *pc2, *pQKs;
    cudaGetSymbolAddress(&pK,  g_K);
    cudaGetSymbolAddress(&pV,  g_V);
    cudaGetSymbolAddress(&pW2, g_W2);
    cudaGetSymbolAddress(&pc2, g_c2);
    cudaGetSymbolAddress(&pQKs, g_QKs);

    reset_mask_kernel<<<(Bq * Lq + 255) / 256, 256>>>();

    // K = keys @ Wk^T + bk ; V = values @ Wv^T + bv   (M=16384,N=1024,K=1024)
    {
        dim3 grid(DM / 128, (Bq * Sq) / 128, 1);
        sgemm_nt<<<grid, 256>>>(keys,   Wk, bk, (float*)pK, Bq * Sq, DM, DM, 0, 0, 0, 0);
        sgemm_nt<<<grid, 256>>>(values, Wv, bv, (float*)pV, Bq * Sq, DM, DM, 0, 0, 0, 0);
    }

    build_w2_kernel<<<Bq * NH, 256>>>(Wq, bq, idx);

    // QKs[b] = queries[b] @ W2[b]^T + c2[b]   (M=4096,N=640,K=1024), batched over b
    {
        dim3 grid((NH * SK) / 128, Lq / 128, Bq);
        sgemm_nt<<<grid, 256>>>(queries, (const float*)pW2, (const float*)pc2,
                                (float*)pQKs, Lq, NH * SK, DM,
                                (size_t)Lq * DM, (size_t)NH * SK * DM,
                                (size_t)NH * SK, (size_t)Lq * NH * SK);
    }

    reduce_m_kernel<<<(Bq * Lq * NH) / 8, 256>>>();
    topk_kernel<<<Bq * NH, 256>>>();
    qred_kernel<<<Bq * NH * NT, 256>>>(queries, Wq, bq);
    attn_kernel<<<Bq * NH, 256>>>();
    out_kernel<<<Bq * Lq, 256>>>(Wo, bo, out);
}

// round 6
// speedup vs baseline: 2.0873x; 2.0854x over previous
#include <cuda_runtime.h>
#include <cuda_bf16.h>
#include <cstdint>

#define Bq 4
#define Lq 4096
#define Sq 4096
#define DM 1024
#define NH 16
#define DKq 64
#define SK 40
#define NT 40
#define FSCALE 0.125f
#define NCH 8
#define SCH 512

// GEMM tiling
#define BKg 32
#define ASTR 40                       // padded smem stride (bf16 elems)
#define TILE_B (128 * ASTR * 2)       // 10240 bytes per 128x32 tile
#define STAGE_B (4 * TILE_B)          // Ah|Al|Wh|Wl = 40960
#define SMEM_MMA (2 * STAGE_B)        // 81920
#define NKg (DM / BKg)                // 32

// ---------------- scratch ----------------------------------------------------
__device__ float    g_K[(size_t)Bq*Sq*DM];
__device__ float    g_V[(size_t)Bq*Sq*DM];
__device__ float    g_c2[Bq*NH*SK];
__device__ float    g_QKs[(size_t)Bq*Lq*NH*SK];
__device__ float    g_Mv[Bq*NH*Lq];
__device__ int      g_Mtop[Bq*NH*NT];
__device__ float    g_Qred[(size_t)Bq*NH*NT*DKq];
__device__ float    g_ctx[(size_t)Bq*NH*NT*DKq];
__device__ unsigned g_mask[Bq*Lq];
__device__ int      g_tslot[(size_t)Bq*Lq*NH];
__device__ float    g_pm[Bq*NH*NCH*NT];
__device__ float    g_pl[Bq*NH*NCH*NT];
__device__ float    g_pctx[(size_t)Bq*NH*NCH*NT*DKq];

__device__ __nv_bfloat16 g_qh[(size_t)Bq*Lq*DM], g_ql[(size_t)Bq*Lq*DM];
__device__ __nv_bfloat16 g_kh[(size_t)Bq*Sq*DM], g_kl[(size_t)Bq*Sq*DM];
__device__ __nv_bfloat16 g_vh[(size_t)Bq*Sq*DM], g_vl[(size_t)Bq*Sq*DM];
__device__ __nv_bfloat16 g_wkh[DM*DM], g_wkl[DM*DM];
__device__ __nv_bfloat16 g_wvh[DM*DM], g_wvl[DM*DM];
__device__ __nv_bfloat16 g_w2h[(size_t)Bq*NH*SK*DM], g_w2l[(size_t)Bq*NH*SK*DM];

// ---------------- helpers ----------------------------------------------------
__device__ __forceinline__ uint32_t smem_u32(const void* p) {
    uint32_t a;
    asm("{ .reg .u64 t; cvta.to.shared.u64 t, %1; cvt.u32.u64 %0, t; }" : "=r"(a) : "l"(p));
    return a;
}
__device__ __forceinline__ void cp16(uint32_t sa, const void* gp) {
    asm volatile("cp.async.cg.shared.global [%0], [%1], 16;" :: "r"(sa), "l"(gp) : "memory");
}
__device__ __forceinline__ uint32_t lds32(uint32_t addr) {
    uint32_t v;
    asm volatile("ld.shared.b32 %0, [%1];" : "=r"(v) : "r"(addr));
    return v;
}
__device__ __forceinline__ void mma_bf16(float* d, const uint32_t* a, const uint32_t* b) {
    asm volatile(
        "mma.sync.aligned.m16n8k16.row.col.f32.bf16.bf16.f32 "
        "{%0,%1,%2,%3}, {%4,%5,%6,%7}, {%8,%9}, {%0,%1,%2,%3};"
        : "+f"(d[0]), "+f"(d[1]), "+f"(d[2]), "+f"(d[3])
        : "r"(a[0]), "r"(a[1]), "r"(a[2]), "r"(a[3]), "r"(b[0]), "r"(b[1]));
}

// ---------------- small kernels ---------------------------------------------
__global__ void reset_mask_kernel() {
    int i = blockIdx.x * 256 + threadIdx.x;
    if (i < Bq * Lq) g_mask[i] = 0u;
}

__global__ __launch_bounds__(256) void split_kernel(
    const float4* __restrict__ x, uint2* __restrict__ hi, uint2* __restrict__ lo, int n4)
{
    int i = blockIdx.x * 256 + threadIdx.x;
    if (i >= n4) return;
    float4 v = x[i];
    float vv[4] = {v.x, v.y, v.z, v.w};
    unsigned h[4], l[4];
#pragma unroll
    for (int j = 0; j < 4; j++) {
        __nv_bfloat16 hb = __float2bfloat16_rn(vv[j]);
        float r = vv[j] - __bfloat162float(hb);
        h[j] = __bfloat16_as_ushort(hb);
        l[j] = __bfloat16_as_ushort(__float2bfloat16_rn(r));
    }
    hi[i] = make_uint2(h[0] | (h[1] << 16), h[2] | (h[3] << 16));
    lo[i] = make_uint2(l[0] | (l[1] << 16), l[2] | (l[3] << 16));
}

// ---------------- HMMA split-bf16 GEMM: C = A @ W^T + bias -------------------
// 128x128 CTA tile, 8 warps (4x2), warp tile 32x64, BK=32, double buffered.
__device__ __forceinline__ void load_stage_mma(
    uint32_t sbase, int st,
    const __nv_bfloat16* Ah, const __nv_bfloat16* Al,
    const __nv_bfloat16* Wh, const __nv_bfloat16* Wl, int k0, int tid)
{
    uint32_t base = sbase + st * STAGE_B;
    const __nv_bfloat16* srcs[4] = {Ah + k0, Al + k0, Wh + k0, Wl + k0};
#pragma unroll
    for (int t = 0; t < 4; t++) {
        const __nv_bfloat16* g = srcs[t];
        uint32_t tb = base + t * TILE_B;
#pragma unroll
        for (int i = 0; i < 2; i++) {
            int id = tid + i * 256;               // 0..511
            int row = id >> 2, ch = id & 3;       // 4x16B chunks = 32 bf16/row
            cp16(tb + row * (ASTR * 2) + ch * 16, g + (size_t)row * DM + ch * 8);
        }
    }
    asm volatile("cp.async.commit_group;" ::: "memory");
}

__global__ __launch_bounds__(256) void gemm_mma_kernel(
    const __nv_bfloat16* __restrict__ Ah, const __nv_bfloat16* __restrict__ Al,
    const __nv_bfloat16* __restrict__ Wh, const __nv_bfloat16* __restrict__ Wl,
    const float* __restrict__ bias, float* __restrict__ C,
    int ldc, size_t aB, size_t wB, size_t bB, size_t cB)
{
    extern __shared__ __align__(16) char smem[];
    int tid = threadIdx.x, wid = tid >> 5, lane = tid & 31;
    int wm = wid & 3, wn = wid >> 2;              // warp grid 4x2
    int qr = lane >> 2, qc = lane & 3;
    int b = blockIdx.z;

    size_t aoff = (size_t)b * aB + (size_t)blockIdx.y * 128 * DM;
    size_t woff = (size_t)b * wB + (size_t)blockIdx.x * 128 * DM;
    Ah += aoff; Al += aoff; Wh += woff; Wl += woff;
    const float* bias_p = bias + (size_t)b * bB + blockIdx.x * 128;
    float* Cp = C + (size_t)b * cB + (size_t)blockIdx.y * 128 * ldc + blockIdx.x * 128;

    uint32_t sb = smem_u32(smem);

    float acc[2][8][4];
#pragma unroll
    for (int m = 0; m < 2; m++)
#pragma unroll
        for (int f = 0; f < 8; f++)
#pragma unroll
            for (int i = 0; i < 4; i++) acc[m][f][i] = 0.f;

    load_stage_mma(sb, 0, Ah, Al, Wh, Wl, 0, tid);
    load_stage_mma(sb, 1, Ah, Al, Wh, Wl, BKg, tid);

    for (int kt = 0; kt < NKg; kt++) {
        asm volatile("cp.async.wait_group 1;" ::: "memory");
        __syncthreads();

        uint32_t stb = sb + (kt & 1) * STAGE_B;
        uint32_t sAh = stb, sAl = stb + TILE_B;
        uint32_t sWh = stb + 2 * TILE_B, sWl = stb + 3 * TILE_B;

#pragma unroll
        for (int kk = 0; kk < BKg; kk += 16) {
            uint32_t ah[2][4], al[2][4], wh2[8][2], wl2[8][2];
#pragma unroll
            for (int m = 0; m < 2; m++) {
                int r0 = wm * 32 + m * 16 + qr;
                uint32_t o00 = (uint32_t)((r0 * ASTR + kk + qc * 2) * 2);
                uint32_t o10 = o00 + 8 * ASTR * 2;
                ah[m][0] = lds32(sAh + o00);  ah[m][1] = lds32(sAh + o10);
                ah[m][2] = lds32(sAh + o00 + 16); ah[m][3] = lds32(sAh + o10 + 16);
                al[m][0] = lds32(sAl + o00);  al[m][1] = lds32(sAl + o10);
                al[m][2] = lds32(sAl + o00 + 16); al[m][3] = lds32(sAl + o10 + 16);
            }
#pragma unroll
            for (int f = 0; f < 8; f++) {
                int n = wn * 64 + f * 8 + qr;
                uint32_t o = (uint32_t)((n * ASTR + kk + qc * 2) * 2);
                wh2[f][0] = lds32(sWh + o); wh2[f][1] = lds32(sWh + o + 16);
                wl2[f][0] = lds32(sWl + o); wl2[f][1] = lds32(sWl + o + 16);
            }
#pragma unroll
            for (int m = 0; m < 2; m++)
#pragma unroll
                for (int f = 0; f < 8; f++) {
                    mma_bf16(acc[m][f], ah[m], wh2[f]);
                    mma_bf16(acc[m][f], ah[m], wl2[f]);
                    mma_bf16(acc[m][f], al[m], wh2[f]);
                }
        }
        __syncthreads();
        if (kt + 2 < NKg)
            load_stage_mma(sb, kt & 1, Ah, Al, Wh, Wl, (kt + 2) * BKg, tid);
        else
            asm volatile("cp.async.commit_group;" ::: "memory");  // keep group count in sync
    }

#pragma unroll
    for (int m = 0; m < 2; m++) {
        float* Crow0 = Cp + (size_t)(wm * 32 + m * 16 + qr) * ldc;
        float* Crow1 = Crow0 + 8 * ldc;
#pragma unroll
        for (int f = 0; f < 8; f++) {
            int col = wn * 64 + f * 8 + qc * 2;
            float b0 = bias_p[col], b1 = bias_p[col + 1];
            float2 v0 = make_float2(acc[m][f][0] + b0, acc[m][f][1] + b1);
            float2 v1 = make_float2(acc[m][f][2] + b0, acc[m][f][3] + b1);
            *(float2*)(Crow0 + col) = v0;
            *(float2*)(Crow1 + col) = v1;
        }
    }
}

// ---------------- W2 build (spill-free, emits bf16 hi/lo) -------------------
__global__ __launch_bounds__(256) void build_w2_kernel(
    const float* __restrict__ Wq, const float* __restrict__ bq,
    const int* __restrict__ idx)
{
    int bh = blockIdx.x;
    int b = bh / NH, h = bh % NH;
    __shared__ float ks[SK * DKq];
    int tid = threadIdx.x;
    for (int i = tid; i < SK * DKq; i += 256) {
        int s = i / DKq, d = i % DKq;
        ks[i] = g_K[((size_t)b * Sq + idx[s]) * DM + h * DKq + d];
    }
    __syncthreads();
    if (tid < SK) {
        float c = 0.f;
#pragma unroll
        for (int d = 0; d < DKq; d++) c += bq[h * DKq + d] * ks[tid * DKq + d];
        g_c2[bh * SK + tid] = c;
    }
    for (int p = 0; p < 4; p++) {
        int n = p * 256 + tid;
        for (int sb = 0; sb < 5; sb++) {
            float acc[8];
#pragma unroll
            for (int s8 = 0; s8 < 8; s8++) acc[s8] = 0.f;
            for (int d = 0; d < DKq; d++) {
                float w = Wq[(size_t)(h * DKq + d) * DM + n];
#pragma unroll
                for (int s8 = 0; s8 < 8; s8++) acc[s8] += w * ks[(sb * 8 + s8) * DKq + d];
            }
#pragma unroll
            for (int s8 = 0; s8 < 8; s8++) {
                size_t o = ((size_t)b * NH * SK + h * SK + sb * 8 + s8) * DM + n;
                float v = acc[s8];
                __nv_bfloat16 hb = __float2bfloat16_rn(v);
                g_w2h[o] = hb;
                g_w2l[o] = __float2bfloat16_rn(v - __bfloat162float(hb));
            }
        }
    }
}

// ---------------- M = max - mean --------------------------------------------
__global__ __launch_bounds__(256) void reduce_m_kernel() {
    int wg = blockIdx.x * 8 + (threadIdx.x >> 5);
    int lane = threadIdx.x & 31;
    int h = wg % NH;
    int bl = wg / NH;
    int b = bl / Lq, l = bl % Lq;
    const float* p = g_QKs + (size_t)bl * (NH * SK) + h * SK;
    float v0 = p[lane];
    float v1 = (lane < SK - 32) ? p[32 + lane] : -3.0e38f;
    float mx = fmaxf(v0, v1);
    float sm = v0 + ((lane < SK - 32) ? p[32 + lane] : 0.f);
#pragma unroll
    for (int o = 16; o; o >>= 1) {
        mx = fmaxf(mx, __shfl_xor_sync(~0u, mx, o));
        sm += __shfl_xor_sync(~0u, sm, o);
    }
    if (lane == 0)
        g_Mv[((size_t)b * NH + h) * Lq + l] = mx - sm * (1.0f / SK);
}

// ---------------- top-40 -----------------------------------------------------
__global__ __launch_bounds__(256) void topk_kernel() {
    int bh = blockIdx.x;
    int b = bh / NH, h = bh % NH;
    __shared__ float vals[Lq];
    __shared__ float rv[256];
    __shared__ int   ri[256];
    int tid = threadIdx.x;
    for (int i = tid; i < Lq; i += 256) vals[i] = g_Mv[(size_t)bh * Lq + i];
    __syncthreads();
    for (int t = 0; t < NT; t++) {
        float best = -3.4e38f; int bi = 0;
        for (int i = tid; i < Lq; i += 256) {
            float v = vals[i];
            if (v > best) { best = v; bi = i; }
        }
        rv[tid] = best; ri[tid] = bi;
        __syncthreads();
        for (int s = 128; s > 0; s >>= 1) {
            if (tid < s) {
                float ov = rv[tid + s]; int oi = ri[tid + s];
                if (ov > rv[tid] || (ov == rv[tid] && oi < ri[tid])) {
                    rv[tid] = ov; ri[tid] = oi;
                }
            }
            __syncthreads();
        }
        if (tid == 0) {
            int li = ri[0];
            g_Mtop[bh * NT + t] = li;
            g_tslot[((size_t)b * Lq + li) * NH + h] = t;
            atomicOr(&g_mask[b * Lq + li], 1u << h);
            vals[li] = -3.4e38f;
        }
        __syncthreads();
    }
}

// ---------------- Q_red (exact fp32) ----------------------------------------
__global__ __launch_bounds__(256) void qred_kernel(
    const float* __restrict__ queries, const float* __restrict__ Wq,
    const float* __restrict__ bq)
{
    int gb = blockIdx.x;
    int t = gb % NT; int bh = gb / NT;
    int h = bh % NH; int b = bh / NH;
    int l = g_Mtop[bh * NT + t];
    __shared__ float qrow[DM];
    int tid = threadIdx.x;
    ((float4*)qrow)[tid] = ((const float4*)(queries + ((size_t)b * Lq + l) * DM))[tid];
    __syncthreads();
    int warp = tid >> 5, lane = tid & 31;
#pragma unroll
    for (int p = 0; p < 8; p++) {
        int d = p * 8 + warp;
        const float* wrow = Wq + (size_t)(h * DKq + d) * DM;
        float s = 0.f;
#pragma unroll
        for (int it = 0; it < 8; it++) {
            float4 w4 = *(const float4*)(wrow + it * 128 + lane * 4);
            float4 q4 = *(const float4*)(qrow + it * 128 + lane * 4);
            s += w4.x * q4.x + w4.y * q4.y + w4.z * q4.z + w4.w * q4.w;
        }
#pragma unroll
        for (int o = 16; o; o >>= 1) s += __shfl_xor_sync(~0u, s, o);
        if (lane == 0) g_Qred[(size_t)gb * DKq + d] = s + bq[h * DKq + d];
    }
}

// ---------------- flash attention, split-KV ---------------------------------
#define KSP (DKq + 4)
__global__ __launch_bounds__(256) void attn_kernel() {
    int bh = blockIdx.x;
    int chunk = blockIdx.y;
    int b = bh / NH, h = bh % NH;
    __shared__ float Qs[NT * DKq];
    __shared__ float Ks[32 * KSP];
    __shared__ float Vs[32 * DKq];
    __shared__ float Ps[NT * 32];
    int tid = threadIdx.x, warp = tid >> 5, lane = tid & 31;

    for (int i = tid; i < NT * DKq / 4; i += 256)
        ((float4*)Qs)[i] = ((const float4*)(g_Qred + (size_t)bh * NT * DKq))[i];

    float acc0[5], acc1[5], mrow[5], lrow[5];
#pragma unroll
    for (int r = 0; r < 5; r++) { acc0[r] = 0.f; acc1[r] = 0.f; mrow[r] = -3.0e38f; lrow[r] = 0.f; }

    int sbeg = chunk * SCH, send = sbeg + SCH;
    for (int s0 = sbeg; s0 < send; s0 += 32) {
        __syncthreads();
#pragma unroll
        for (int ld = 0; ld < 2; ld++) {
            int v = tid + ld * 256;
            int r = v >> 4, c4 = (v & 15) * 4;
            size_t gbase = ((size_t)b * Sq + s0 + r) * DM + h * DKq + c4;
            float4 kf = *(const float4*)(g_K + gbase);
            Ks[r * KSP + c4 + 0] = kf.x; Ks[r * KSP + c4 + 1] = kf.y;
            Ks[r * KSP + c4 + 2] = kf.z; Ks[r * KSP + c4 + 3] = kf.w;
            float4 vf = *(const float4*)(g_V + gbase);
            *(float4*)&Vs[r * DKq + c4] = vf;
        }
        __syncthreads();

        float score[5];
#pragma unroll
        for (int r = 0; r < 5; r++) score[r] = 0.f;
#pragma unroll
        for (int d4 = 0; d4 < DKq; d4 += 4) {
            float4 k4 = *(float4*)&Ks[lane * KSP + d4];
#pragma unroll
            for (int r = 0; r < 5; r++) {
                float4 q4 = *(float4*)&Qs[(warp * 5 + r) * DKq + d4];
                score[r] += q4.x * k4.x + q4.y * k4.y + q4.z * k4.z + q4.w * k4.w;
            }
        }
#pragma unroll
        for (int r = 0; r < 5; r++) {
            float sc = score[r] * FSCALE;
            float mx = sc;
#pragma unroll
            for (int o = 16; o; o >>= 1) mx = fmaxf(mx, __shfl_xor_sync(~0u, mx, o));
            float mnew  = fmaxf(mrow[r], mx);
            float p     = expf(sc - mnew);
            float alpha = expf(mrow[r] - mnew);
            float psum  = p;
#pragma unroll
            for (int o = 16; o; o >>= 1) psum += __shfl_xor_sync(~0u, psum, o);
            lrow[r] = lrow[r] * alpha + psum;
            mrow[r] = mnew;
            acc0[r] *= alpha; acc1[r] *= alpha;
            Ps[(warp * 5 + r) * 32 + lane] = p;
        }
        __syncwarp();
#pragma unroll 4
        for (int ss = 0; ss < 32; ss++) {
            float2 v2 = *(float2*)&Vs[ss * DKq + lane * 2];
#pragma unroll
            for (int r = 0; r < 5; r++) {
                float pr = Ps[(warp * 5 + r) * 32 + ss];
                acc0[r] += pr * v2.x; acc1[r] += pr * v2.y;
            }
        }
        __syncwarp();
    }
#pragma unroll
    for (int r = 0; r < 5; r++) {
        int t = warp * 5 + r;
        float2 o2; o2.x = acc0[r]; o2.y = acc1[r];
        *(float2*)(g_pctx + ((size_t)(bh * NCH + chunk) * NT + t) * DKq + lane * 2) = o2;
        if (lane == 0) {
            g_pm[(bh * NCH + chunk) * NT + t] = mrow[r];
            g_pl[(bh * NCH + chunk) * NT + t] = lrow[r];
        }
    }
}

// ---------------- LSE merge --------------------------------------------------
__global__ __launch_bounds__(256) void merge_kernel() {
    int bh = blockIdx.x;
    int tid = threadIdx.x;
    __shared__ float sm_m[NCH * NT], sm_l[NCH * NT];
    for (int i = tid; i < NCH * NT; i += 256) {
        sm_m[i] = g_pm[bh * NCH * NT + i];
        sm_l[i] = g_pl[bh * NCH * NT + i];
    }
    __syncthreads();
    for (int i = tid; i < NT * DKq; i += 256) {
        int t = i >> 6, d = i & 63;
        float M = -3.0e38f;
#pragma unroll
        for (int c = 0; c < NCH; c++) M = fmaxf(M, sm_m[c * NT + t]);
        float L = 0.f, a = 0.f;
#pragma unroll
        for (int c = 0; c < NCH; c++) {
            float w = expf(sm_m[c * NT + t] - M);
            L += w * sm_l[c * NT + t];
            a += w * g_pctx[((size_t)(bh * NCH + c) * NT + t) * DKq + d];
        }
        g_ctx[((size_t)bh * NT + t) * DKq + d] = a / L;
    }
}

// ---------------- sparse output projection ----------------------------------
__global__ __launch_bounds__(256) void out_kernel(
    const float* __restrict__ Wo, const float* __restrict__ bo,
    float* __restrict__ out)
{
    int row = blockIdx.x;
    int b = row / Lq;
    int tid = threadIdx.x, warp = tid >> 5, lane = tid & 31;
    unsigned msk = g_mask[row];
    __shared__ float osm[DM];
    __shared__ float csm[DKq];

    ((float4*)osm)[tid] = ((const float4*)bo)[tid];
    __syncthreads();

    if (msk) {
        for (int h = 0; h < NH; h++) {
            if (!((msk >> h) & 1u)) continue;
            int t = g_tslot[(size_t)row * NH + h];
            if (tid < DKq / 4)
                ((float4*)csm)[tid] =
                    ((const float4*)(g_ctx + ((size_t)(b * NH + h) * NT + t) * DKq))[tid];
            __syncthreads();
            float c0 = csm[lane], c1 = csm[32 + lane];
            for (int j = 0; j < 128; j++) {
                int m = warp * 128 + j;
                const float* wrow = Wo + (size_t)m * DM + h * DKq;
                float s = wrow[lane] * c0 + wrow[32 + lane] * c1;
#pragma unroll
                for (int o = 16; o; o >>= 1) s += __shfl_xor_sync(~0u, s, o);
                if (lane == 0) osm[m] += s;
            }
            __syncthreads();
        }
    }
    ((float4*)(out + (size_t)row * DM))[tid] = ((float4*)osm)[tid];
}

// ---------------- launch -----------------------------------------------------
extern "C" void kernel_launch(void* const* d_in, const int* in_sizes, int n_in,
                              void* d_out, int out_size)
{
    const float* queries = (const float*)d_in[0];
    const float* keys    = (const float*)d_in[1];
    const float* values  = (const float*)d_in[2];
    const float* Wq      = (const float*)d_in[3];
    const float* bq      = (const float*)d_in[4];
    const float* Wk      = (const float*)d_in[5];
    const float* bk      = (const float*)d_in[6];
    const float* Wv      = (const float*)d_in[7];
    const float* bv      = (const float*)d_in[8];
    const float* Wo      = (const float*)d_in[9];
    const float* bo      = (const float*)d_in[10];
    const int*   idx     = (const int*)d_in[11];
    float* out = (float*)d_out;

    cudaFuncSetAttribute(gemm_mma_kernel,
                         cudaFuncAttributeMaxDynamicSharedMemorySize, SMEM_MMA);

    void *pK, *pV, *pc2, *pQKs;
    void *pqh, *pql, *pkh, *pkl, *pvh, *pvl, *pwkh, *pwkl, *pwvh, *pwvl, *pw2h, *pw2l;
    cudaGetSymbolAddress(&pK,  g_K);
    cudaGetSymbolAddress(&pV,  g_V);
    cudaGetSymbolAddress(&pc2, g_c2);
    cudaGetSymbolAddress(&pQKs, g_QKs);
    cudaGetSymbolAddress(&pqh, g_qh);   cudaGetSymbolAddress(&pql, g_ql);
    cudaGetSymbolAddress(&pkh, g_kh);   cudaGetSymbolAddress(&pkl, g_kl);
    cudaGetSymbolAddress(&pvh, g_vh);   cudaGetSymbolAddress(&pvl, g_vl);
    cudaGetSymbolAddress(&pwkh, g_wkh); cudaGetSymbolAddress(&pwkl, g_wkl);
    cudaGetSymbolAddress(&pwvh, g_wvh); cudaGetSymbolAddress(&pwvl, g_wvl);
    cudaGetSymbolAddress(&pw2h, g_w2h); cudaGetSymbolAddress(&pw2l, g_w2l);

    reset_mask_kernel<<<(Bq * Lq + 255) / 256, 256>>>();

    // bf16 hi/lo splits
    {
        int nBig = Bq * Lq * DM / 4;
        int nW   = DM * DM / 4;
        split_kernel<<<(nBig + 255) / 256, 256>>>((const float4*)keys,
            (uint2*)pkh, (uint2*)pkl, nBig);
        split_kernel<<<(nBig + 255) / 256, 256>>>((const float4*)values,
            (uint2*)pvh, (uint2*)pvl, nBig);
        split_kernel<<<(nBig + 255) / 256, 256>>>((const float4*)queries,
            (uint2*)pqh, (uint2*)pql, nBig);
        split_kernel<<<(nW + 255) / 256, 256>>>((const float4*)Wk,
            (uint2*)pwkh, (uint2*)pwkl, nW);
        split_kernel<<<(nW + 255) / 256, 256>>>((const float4*)Wv,
            (uint2*)pwvh, (uint2*)pwvl, nW);
    }

    // K = keys @ Wk^T + bk ; V = values @ Wv^T + bv  (M=16384, N=1024, K=1024)
    {
        dim3 grid(DM / 128, (Bq * Sq) / 128, 1);
        gemm_mma_kernel<<<grid, 256, SMEM_MMA>>>(
            (const __nv_bfloat16*)pkh, (const __nv_bfloat16*)pkl,
            (const __nv_bfloat16*)pwkh, (const __nv_bfloat16*)pwkl,
            bk, (float*)pK, DM, 0, 0, 0, 0);
        gemm_mma_kernel<<<grid, 256, SMEM_MMA>>>(
            (const __nv_bfloat16*)pvh, (const __nv_bfloat16*)pvl,
            (const __nv_bfloat16*)pwvh, (const __nv_bfloat16*)pwvl,
            bv, (float*)pV, DM, 0, 0, 0, 0);
    }

    build_w2_kernel<<<Bq * NH, 256>>>(Wq, bq, idx);

    // QKs[b] = queries[b] @ W2[b]^T + c2[b]  (M=4096, N=640, K=1024)
    {
        dim3 grid((NH * SK) / 128, Lq / 128, Bq);
        gemm_mma_kernel<<<grid, 256, SMEM_MMA>>>(
            (const __nv_bfloat16*)pqh, (const __nv_bfloat16*)pql,
            (const __nv_bfloat16*)pw2h, (const __nv_bfloat16*)pw2l,
            (const float*)pc2, (float*)pQKs, NH * SK,
            (size_t)Lq * DM, (size_t)NH * SK * DM,
            (size_t)NH * SK, (size_t)Lq * NH * SK);
    }

    reduce_m_kernel<<<(Bq * Lq * NH) / 8, 256>>>();
    topk_kernel<<<Bq * NH, 256>>>();
    qred_kernel<<<Bq * NH * NT, 256>>>(queries, Wq, bq);
    attn_kernel<<<dim3(Bq * NH, NCH), 256>>>();
    merge_kernel<<<Bq * NH, 256>>>();
    out_kernel<<<Bq * Lq, 256>>>(Wo, bo, out);
}

// round 7
// speedup vs baseline: 2.2754x; 1.0901x over previous
#include <cuda_runtime.h>
#include <cuda_bf16.h>
#include <cstdint>

#define Bq 4
#define Lq 4096
#define Sq 4096
#define DM 1024
#define NH 16
#define DKq 64
#define SK 40
#define NT 40
#define FSCALE 0.125f
#define NHT (NH * NT)                 // 640 rows per batch in QW/S/P/Y

// GEMM tiling
#define BKg 32
#define ASTR 40
#define TILE_B (128 * ASTR * 2)
#define STAGE_B (4 * TILE_B)
#define SMEM_MMA (2 * STAGE_B)

// ---------------- scratch ----------------------------------------------------
__device__ float    g_c2[Bq*NH*SK];
__device__ float    g_QKs[(size_t)Bq*Lq*NHT];
__device__ float    g_Mv[Bq*NH*Lq];
__device__ int      g_Mtop[Bq*NH*NT];
__device__ float    g_Qred[(size_t)Bq*NH*NT*DKq];
__device__ float    g_ctx[(size_t)Bq*NH*NT*DKq];
__device__ unsigned g_mask[Bq*Lq];
__device__ int      g_tslot[(size_t)Bq*Lq*NH];
__device__ float    g_S[(size_t)Bq*NHT*Sq];
__device__ float    g_Yp[(size_t)2*Bq*NHT*DM];
__device__ float    g_zb[4096];       // stays zero (never written)

__device__ __nv_bfloat16 g_qh[(size_t)Bq*Lq*DM],  g_ql[(size_t)Bq*Lq*DM];
__device__ __nv_bfloat16 g_kh[(size_t)Bq*Sq*DM],  g_kl[(size_t)Bq*Sq*DM];
__device__ __nv_bfloat16 g_vTh[(size_t)Bq*DM*Sq], g_vTl[(size_t)Bq*DM*Sq];
__device__ __nv_bfloat16 g_w2h[(size_t)Bq*NH*SK*DM], g_w2l[(size_t)Bq*NH*SK*DM];
__device__ __nv_bfloat16 g_qwh[(size_t)Bq*NHT*DM], g_qwl[(size_t)Bq*NHT*DM];
__device__ __nv_bfloat16 g_Ph[(size_t)Bq*NHT*Sq], g_Pl[(size_t)Bq*NHT*Sq];

// ---------------- helpers ----------------------------------------------------
__device__ __forceinline__ uint32_t smem_u32(const void* p) {
    uint32_t a;
    asm("{ .reg .u64 t; cvta.to.shared.u64 t, %1; cvt.u32.u64 %0, t; }" : "=r"(a) : "l"(p));
    return a;
}
__device__ __forceinline__ void cp16(uint32_t sa, const void* gp) {
    asm volatile("cp.async.cg.shared.global [%0], [%1], 16;" :: "r"(sa), "l"(gp) : "memory");
}
__device__ __forceinline__ uint32_t lds32(uint32_t addr) {
    uint32_t v;
    asm volatile("ld.shared.b32 %0, [%1];" : "=r"(v) : "r"(addr));
    return v;
}
__device__ __forceinline__ void mma_bf16(float* d, const uint32_t* a, const uint32_t* b) {
    asm volatile(
        "mma.sync.aligned.m16n8k16.row.col.f32.bf16.bf16.f32 "
        "{%0,%1,%2,%3}, {%4,%5,%6,%7}, {%8,%9}, {%0,%1,%2,%3};"
        : "+f"(d[0]), "+f"(d[1]), "+f"(d[2]), "+f"(d[3])
        : "r"(a[0]), "r"(a[1]), "r"(a[2]), "r"(a[3]), "r"(b[0]), "r"(b[1]));
}
__device__ __forceinline__ void split2(float v, __nv_bfloat16* hp, __nv_bfloat16* lp) {
    __nv_bfloat16 hb = __float2bfloat16_rn(v);
    *hp = hb;
    *lp = __float2bfloat16_rn(v - __bfloat162float(hb));
}

// ---------------- small kernels ---------------------------------------------
__global__ void reset_mask_kernel() {
    int i = blockIdx.x * 256 + threadIdx.x;
    if (i < Bq * Lq) g_mask[i] = 0u;
}

__global__ __launch_bounds__(256) void split_kernel(
    const float4* __restrict__ x, uint2* __restrict__ hi, uint2* __restrict__ lo, int n4)
{
    int i = blockIdx.x * 256 + threadIdx.x;
    if (i >= n4) return;
    float4 v = x[i];
    float vv[4] = {v.x, v.y, v.z, v.w};
    unsigned h[4], l[4];
#pragma unroll
    for (int j = 0; j < 4; j++) {
        __nv_bfloat16 hb = __float2bfloat16_rn(vv[j]);
        float r = vv[j] - __bfloat162float(hb);
        h[j] = __bfloat16_as_ushort(hb);
        l[j] = __bfloat16_as_ushort(__float2bfloat16_rn(r));
    }
    hi[i] = make_uint2(h[0] | (h[1] << 16), h[2] | (h[3] << 16));
    lo[i] = make_uint2(l[0] | (l[1] << 16), l[2] | (l[3] << 16));
}

// values [b][s][m] -> vT hi/lo [b][m][s]
__global__ __launch_bounds__(256) void splitT_kernel(
    const float* __restrict__ x, __nv_bfloat16* __restrict__ hiT,
    __nv_bfloat16* __restrict__ loT)
{
    __shared__ float t[32][33];
    int b = blockIdx.z;
    int m0 = blockIdx.x * 32, s0 = blockIdx.y * 32;
    int tx = threadIdx.x & 31, ty = threadIdx.x >> 5;    // 32 x 8
#pragma unroll
    for (int i = 0; i < 4; i++)
        t[ty + i * 8][tx] = x[((size_t)b * Sq + s0 + ty + i * 8) * DM + m0 + tx];
    __syncthreads();
#pragma unroll
    for (int i = 0; i < 4; i++) {
        float v = t[tx][ty + i * 8];
        size_t o = ((size_t)b * DM + m0 + ty + i * 8) * Sq + s0 + tx;
        __nv_bfloat16 hb = __float2bfloat16_rn(v);
        hiT[o] = hb;
        loT[o] = __float2bfloat16_rn(v - __bfloat162float(hb));
    }
}

// ---------------- HMMA split-bf16 GEMM: C = A @ W^T + bias -------------------
__device__ __forceinline__ void load_stage_mma(
    uint32_t sbase, int st,
    const __nv_bfloat16* Ah, const __nv_bfloat16* Al,
    const __nv_bfloat16* Wh, const __nv_bfloat16* Wl, int k0, int ldk, int tid)
{
    uint32_t base = sbase + st * STAGE_B;
    const __nv_bfloat16* srcs[4] = {Ah + k0, Al + k0, Wh + k0, Wl + k0};
#pragma unroll
    for (int t = 0; t < 4; t++) {
        const __nv_bfloat16* g = srcs[t];
        uint32_t tb = base + t * TILE_B;
#pragma unroll
        for (int i = 0; i < 2; i++) {
            int id = tid + i * 256;
            int row = id >> 2, ch = id & 3;
            cp16(tb + row * (ASTR * 2) + ch * 16, g + (size_t)row * ldk + ch * 8);
        }
    }
    asm volatile("cp.async.commit_group;" ::: "memory");
}

__global__ __launch_bounds__(256) void gemm_mma_kernel(
    const __nv_bfloat16* __restrict__ Ah, const __nv_bfloat16* __restrict__ Al,
    const __nv_bfloat16* __restrict__ Wh, const __nv_bfloat16* __restrict__ Wl,
    const float* __restrict__ bias, float* __restrict__ C,
    int ldc, int ldk, int nkt, int ksplit,
    size_t aB, size_t wB, size_t bB, size_t cB)
{
    extern __shared__ __align__(16) char smem[];
    int tid = threadIdx.x, wid = tid >> 5, lane = tid & 31;
    int wm = wid & 3, wn = wid >> 2;
    int qr = lane >> 2, qc = lane & 3;
    int z = blockIdx.z;
    int b = z / ksplit, ch = z % ksplit;

    size_t aoff = (size_t)b * aB + (size_t)blockIdx.y * 128 * ldk + (size_t)ch * nkt * BKg;
    size_t woff = (size_t)b * wB + (size_t)blockIdx.x * 128 * ldk + (size_t)ch * nkt * BKg;
    Ah += aoff; Al += aoff; Wh += woff; Wl += woff;
    const float* bias_p = bias + (size_t)b * bB + blockIdx.x * 128;
    float* Cp = C + (size_t)z * cB + (size_t)blockIdx.y * 128 * ldc + blockIdx.x * 128;

    uint32_t sb = smem_u32(smem);

    float acc[2][8][4];
#pragma unroll
    for (int m = 0; m < 2; m++)
#pragma unroll
        for (int f = 0; f < 8; f++)
#pragma unroll
            for (int i = 0; i < 4; i++) acc[m][f][i] = 0.f;

    load_stage_mma(sb, 0, Ah, Al, Wh, Wl, 0, ldk, tid);
    load_stage_mma(sb, 1, Ah, Al, Wh, Wl, BKg, ldk, tid);

    for (int kt = 0; kt < nkt; kt++) {
        asm volatile("cp.async.wait_group 1;" ::: "memory");
        __syncthreads();

        uint32_t stb = sb + (kt & 1) * STAGE_B;
        uint32_t sAh = stb, sAl = stb + TILE_B;
        uint32_t sWh = stb + 2 * TILE_B, sWl = stb + 3 * TILE_B;

#pragma unroll
        for (int kk = 0; kk < BKg; kk += 16) {
            uint32_t ah[2][4], al[2][4], wh2[8][2], wl2[8][2];
#pragma unroll
            for (int m = 0; m < 2; m++) {
                int r0 = wm * 32 + m * 16 + qr;
                uint32_t o00 = (uint32_t)((r0 * ASTR + kk + qc * 2) * 2);
                uint32_t o10 = o00 + 8 * ASTR * 2;
                ah[m][0] = lds32(sAh + o00);  ah[m][1] = lds32(sAh + o10);
                ah[m][2] = lds32(sAh + o00 + 16); ah[m][3] = lds32(sAh + o10 + 16);
                al[m][0] = lds32(sAl + o00);  al[m][1] = lds32(sAl + o10);
                al[m][2] = lds32(sAl + o00 + 16); al[m][3] = lds32(sAl + o10 + 16);
            }
#pragma unroll
            for (int f = 0; f < 8; f++) {
                int n = wn * 64 + f * 8 + qr;
                uint32_t o = (uint32_t)((n * ASTR + kk + qc * 2) * 2);
                wh2[f][0] = lds32(sWh + o); wh2[f][1] = lds32(sWh + o + 16);
                wl2[f][0] = lds32(sWl + o); wl2[f][1] = lds32(sWl + o + 16);
            }
#pragma unroll
            for (int m = 0; m < 2; m++)
#pragma unroll
                for (int f = 0; f < 8; f++) {
                    mma_bf16(acc[m][f], ah[m], wh2[f]);
                    mma_bf16(acc[m][f], ah[m], wl2[f]);
                    mma_bf16(acc[m][f], al[m], wh2[f]);
                }
        }
        __syncthreads();
        if (kt + 2 < nkt)
            load_stage_mma(sb, kt & 1, Ah, Al, Wh, Wl, (kt + 2) * BKg, ldk, tid);
        else
            asm volatile("cp.async.commit_group;" ::: "memory");
    }

#pragma unroll
    for (int m = 0; m < 2; m++) {
        float* Crow0 = Cp + (size_t)(wm * 32 + m * 16 + qr) * ldc;
        float* Crow1 = Crow0 + 8 * ldc;
#pragma unroll
        for (int f = 0; f < 8; f++) {
            int col = wn * 64 + f * 8 + qc * 2;
            float b0 = bias_p[col], b1 = bias_p[col + 1];
            *(float2*)(Crow0 + col) = make_float2(acc[m][f][0] + b0, acc[m][f][1] + b1);
            *(float2*)(Crow1 + col) = make_float2(acc[m][f][2] + b0, acc[m][f][3] + b1);
        }
    }
}

// ---------------- build_w2: K_sample slice (in-kernel) + W2 + c2 ------------
__global__ __launch_bounds__(256) void build_w2_kernel(
    const float* __restrict__ keys, const float* __restrict__ Wq,
    const float* __restrict__ Wk, const float* __restrict__ bq,
    const float* __restrict__ bk, const int* __restrict__ idx)
{
    int bh = blockIdx.x;
    int b = bh / NH, h = bh % NH;
    __shared__ float ks[SK * DKq];
    __shared__ float kt[SK][65];
    __shared__ float wt[DKq][65];
    int tid = threadIdx.x, lane = tid & 31, grp = tid >> 5;

    // phase 1: K_sample[s,d] = keys[b, idx[s]] . Wk[h*64+d] + bk
    float acc[5][2];
#pragma unroll
    for (int k = 0; k < 5; k++) { acc[k][0] = 0.f; acc[k][1] = 0.f; }
    for (int m0 = 0; m0 < DM; m0 += 64) {
        __syncthreads();
        for (int i = tid; i < SK * 64; i += 256) {
            int s = i >> 6, mm = i & 63;
            kt[s][mm] = keys[((size_t)b * Sq + idx[s]) * DM + m0 + mm];
        }
        for (int i = tid; i < DKq * 64; i += 256) {
            int d = i >> 6, mm = i & 63;
            wt[d][mm] = Wk[(size_t)(h * DKq + d) * DM + m0 + mm];
        }
        __syncthreads();
#pragma unroll 8
        for (int mm = 0; mm < 64; mm++) {
            float w0 = wt[lane][mm], w1 = wt[lane + 32][mm];
#pragma unroll
            for (int k = 0; k < 5; k++) {
                float a = kt[grp + k * 8][mm];
                acc[k][0] += a * w0;
                acc[k][1] += a * w1;
            }
        }
    }
    __syncthreads();
#pragma unroll
    for (int k = 0; k < 5; k++) {
        int s = grp + k * 8;
        ks[s * DKq + lane]      = acc[k][0] + bk[h * DKq + lane];
        ks[s * DKq + lane + 32] = acc[k][1] + bk[h * DKq + lane + 32];
    }
    __syncthreads();

    // phase 2: c2 = bq . K_sample ; W2 = Wq_h^T @ K_sample (hi/lo bf16)
    if (tid < SK) {
        float c = 0.f;
#pragma unroll
        for (int d = 0; d < DKq; d++) c += bq[h * DKq + d] * ks[tid * DKq + d];
        g_c2[bh * SK + tid] = c;
    }
    for (int p = 0; p < 4; p++) {
        int n = p * 256 + tid;
        for (int sb = 0; sb < 5; sb++) {
            float a2[8];
#pragma unroll
            for (int s8 = 0; s8 < 8; s8++) a2[s8] = 0.f;
            for (int d = 0; d < DKq; d++) {
                float w = Wq[(size_t)(h * DKq + d) * DM + n];
#pragma unroll
                for (int s8 = 0; s8 < 8; s8++) a2[s8] += w * ks[(sb * 8 + s8) * DKq + d];
            }
#pragma unroll
            for (int s8 = 0; s8 < 8; s8++) {
                size_t o = ((size_t)b * NH * SK + h * SK + sb * 8 + s8) * DM + n;
                split2(a2[s8], &g_w2h[o], &g_w2l[o]);
            }
        }
    }
}

// ---------------- M = max - mean --------------------------------------------
__global__ __launch_bounds__(256) void reduce_m_kernel() {
    int wg = blockIdx.x * 8 + (threadIdx.x >> 5);
    int lane = threadIdx.x & 31;
    int h = wg % NH;
    int bl = wg / NH;
    int b = bl / Lq, l = bl % Lq;
    const float* p = g_QKs + (size_t)bl * NHT + h * SK;
    float v0 = p[lane];
    float v1 = (lane < SK - 32) ? p[32 + lane] : -3.0e38f;
    float mx = fmaxf(v0, v1);
    float sm = v0 + ((lane < SK - 32) ? p[32 + lane] : 0.f);
#pragma unroll
    for (int o = 16; o; o >>= 1) {
        mx = fmaxf(mx, __shfl_xor_sync(~0u, mx, o));
        sm += __shfl_xor_sync(~0u, sm, o);
    }
    if (lane == 0)
        g_Mv[((size_t)b * NH + h) * Lq + l] = mx - sm * (1.0f / SK);
}

// ---------------- top-40 -----------------------------------------------------
__global__ __launch_bounds__(256) void topk_kernel() {
    int bh = blockIdx.x;
    int b = bh / NH, h = bh % NH;
    __shared__ float vals[Lq];
    __shared__ float rv[256];
    __shared__ int   ri[256];
    int tid = threadIdx.x;
    for (int i = tid; i < Lq; i += 256) vals[i] = g_Mv[(size_t)bh * Lq + i];
    __syncthreads();
    for (int t = 0; t < NT; t++) {
        float best = -3.4e38f; int bi = 0;
        for (int i = tid; i < Lq; i += 256) {
            float v = vals[i];
            if (v > best) { best = v; bi = i; }
        }
        rv[tid] = best; ri[tid] = bi;
        __syncthreads();
        for (int s = 128; s > 0; s >>= 1) {
            if (tid < s) {
                float ov = rv[tid + s]; int oi = ri[tid + s];
                if (ov > rv[tid] || (ov == rv[tid] && oi < ri[tid])) {
                    rv[tid] = ov; ri[tid] = oi;
                }
            }
            __syncthreads();
        }
        if (tid == 0) {
            int li = ri[0];
            g_Mtop[bh * NT + t] = li;
            g_tslot[((size_t)b * Lq + li) * NH + h] = t;
            atomicOr(&g_mask[b * Lq + li], 1u << h);
            vals[li] = -3.4e38f;
        }
        __syncthreads();
    }
}

// ---------------- Q_red (exact fp32) ----------------------------------------
__global__ __launch_bounds__(256) void qred_kernel(
    const float* __restrict__ queries, const float* __restrict__ Wq,
    const float* __restrict__ bq)
{
    int gb = blockIdx.x;
    int t = gb % NT; int bh = gb / NT;
    int h = bh % NH; int b = bh / NH;
    int l = g_Mtop[bh * NT + t];
    __shared__ float qrow[DM];
    int tid = threadIdx.x;
    ((float4*)qrow)[tid] = ((const float4*)(queries + ((size_t)b * Lq + l) * DM))[tid];
    __syncthreads();
    int warp = tid >> 5, lane = tid & 31;
#pragma unroll
    for (int p = 0; p < 8; p++) {
        int d = p * 8 + warp;
        const float* wrow = Wq + (size_t)(h * DKq + d) * DM;
        float s = 0.f;
#pragma unroll
        for (int it = 0; it < 8; it++) {
            float4 w4 = *(const float4*)(wrow + it * 128 + lane * 4);
            float4 q4 = *(const float4*)(qrow + it * 128 + lane * 4);
            s += w4.x * q4.x + w4.y * q4.y + w4.z * q4.z + w4.w * q4.w;
        }
#pragma unroll
        for (int o = 16; o; o >>= 1) s += __shfl_xor_sync(~0u, s, o);
        if (lane == 0) g_Qred[(size_t)gb * DKq + d] = s + bq[h * DKq + d];
    }
}

// ---------------- QW = Qred @ Wk_h  (hi/lo bf16) ----------------------------
__global__ __launch_bounds__(256) void qw_kernel(const float* __restrict__ Wk) {
    int bh = blockIdx.x;
    int h = bh % NH;
    __shared__ float qs[NT * DKq];
    int tid = threadIdx.x;
    for (int i = tid; i < NT * DKq; i += 256)
        qs[i] = g_Qred[(size_t)bh * NT * DKq + i];
    __syncthreads();
    for (int p = 0; p < 4; p++) {
        int n = p * 256 + tid;
        for (int sb = 0; sb < 5; sb++) {
            float a2[8];
#pragma unroll
            for (int t8 = 0; t8 < 8; t8++) a2[t8] = 0.f;
            for (int d = 0; d < DKq; d++) {
                float w = Wk[(size_t)(h * DKq + d) * DM + n];
#pragma unroll
                for (int t8 = 0; t8 < 8; t8++) a2[t8] += w * qs[(sb * 8 + t8) * DKq + d];
            }
#pragma unroll
            for (int t8 = 0; t8 < 8; t8++) {
                size_t o = ((size_t)bh * NT + sb * 8 + t8) * DM + n;
                split2(a2[t8], &g_qwh[o], &g_qwl[o]);
            }
        }
    }
}

// ---------------- softmax over S rows -> P hi/lo ----------------------------
__global__ __launch_bounds__(256) void softmax_kernel() {
    int r = blockIdx.x;                  // b*640 + ht
    const float* Sp = g_S + (size_t)r * Sq;
    int tid = threadIdx.x;
    float v[16];
    float mx = -3.0e38f;
#pragma unroll
    for (int i = 0; i < 16; i++) {
        v[i] = Sp[tid + i * 256] * FSCALE;
        mx = fmaxf(mx, v[i]);
    }
    __shared__ float red[256];
    red[tid] = mx; __syncthreads();
    for (int s = 128; s; s >>= 1) {
        if (tid < s) red[tid] = fmaxf(red[tid], red[tid + s]);
        __syncthreads();
    }
    mx = red[0]; __syncthreads();
    float sm = 0.f;
#pragma unroll
    for (int i = 0; i < 16; i++) { v[i] = expf(v[i] - mx); sm += v[i]; }
    red[tid] = sm; __syncthreads();
    for (int s = 128; s; s >>= 1) {
        if (tid < s) red[tid] += red[tid + s];
        __syncthreads();
    }
    float inv = 1.0f / red[0];
#pragma unroll
    for (int i = 0; i < 16; i++) {
        float p = v[i] * inv;
        size_t o = (size_t)r * Sq + tid + i * 256;
        __nv_bfloat16 hb = __float2bfloat16_rn(p);
        g_Ph[o] = hb;
        g_Pl[o] = __float2bfloat16_rn(p - __bfloat162float(hb));
    }
}

// ---------------- ctx = (Yp0+Yp1) @ Wv_h^T + bv -----------------------------
__global__ __launch_bounds__(256) void ctx_kernel(
    const float* __restrict__ Wv, const float* __restrict__ bv)
{
    int gb = blockIdx.x;              // bh*NT + t
    int t = gb % NT; int bh = gb / NT;
    int h = bh % NH; int b = bh / NH;
    int ht = h * NT + t;
    __shared__ float y[DM];
    int tid = threadIdx.x;
    const float4* r0 = (const float4*)(g_Yp + ((size_t)(b * 2 + 0) * NHT + ht) * DM);
    const float4* r1 = (const float4*)(g_Yp + ((size_t)(b * 2 + 1) * NHT + ht) * DM);
    float4 a = r0[tid], c = r1[tid];
    ((float4*)y)[tid] = make_float4(a.x + c.x, a.y + c.y, a.z + c.z, a.w + c.w);
    __syncthreads();
    int warp = tid >> 5, lane = tid & 31;
#pragma unroll
    for (int p = 0; p < 8; p++) {
        int d = p * 8 + warp;
        const float* wrow = Wv + (size_t)(h * DKq + d) * DM;
        float s = 0.f;
#pragma unroll
        for (int it = 0; it < 8; it++) {
            float4 w4 = *(const float4*)(wrow + it * 128 + lane * 4);
            float4 q4 = *(const float4*)(y + it * 128 + lane * 4);
            s += w4.x * q4.x + w4.y * q4.y + w4.z * q4.z + w4.w * q4.w;
        }
#pragma unroll
        for (int o = 16; o; o >>= 1) s += __shfl_xor_sync(~0u, s, o);
        if (lane == 0) g_ctx[(size_t)gb * DKq + d] = s + bv[h * DKq + d];
    }
}

// ---------------- sparse output projection ----------------------------------
__global__ __launch_bounds__(256) void out_kernel(
    const float* __restrict__ Wo, const float* __restrict__ bo,
    float* __restrict__ out)
{
    int row = blockIdx.x;
    int b = row / Lq;
    int tid = threadIdx.x, warp = tid >> 5, lane = tid & 31;
    unsigned msk = g_mask[row];
    __shared__ float osm[DM];
    __shared__ float csm[DKq];

    ((float4*)osm)[tid] = ((const float4*)bo)[tid];
    __syncthreads();

    if (msk) {
        for (int h = 0; h < NH; h++) {
            if (!((msk >> h) & 1u)) continue;
            int t = g_tslot[(size_t)row * NH + h];
            if (tid < DKq / 4)
                ((float4*)csm)[tid] =
                    ((const float4*)(g_ctx + ((size_t)(b * NH + h) * NT + t) * DKq))[tid];
            __syncthreads();
            float c0 = csm[lane], c1 = csm[32 + lane];
            for (int j = 0; j < 128; j++) {
                int m = warp * 128 + j;
                const float* wrow = Wo + (size_t)m * DM + h * DKq;
                float s = wrow[lane] * c0 + wrow[32 + lane] * c1;
#pragma unroll
                for (int o = 16; o; o >>= 1) s += __shfl_xor_sync(~0u, s, o);
                if (lane == 0) osm[m] += s;
            }
            __syncthreads();
        }
    }
    ((float4*)(out + (size_t)row * DM))[tid] = ((float4*)osm)[tid];
}

// ---------------- launch -----------------------------------------------------
extern "C" void kernel_launch(void* const* d_in, const int* in_sizes, int n_in,
                              void* d_out, int out_size)
{
    const float* queries = (const float*)d_in[0];
    const float* keys    = (const float*)d_in[1];
    const float* values  = (const float*)d_in[2];
    const float* Wq      = (const float*)d_in[3];
    const float* bq      = (const float*)d_in[4];
    const float* Wk      = (const float*)d_in[5];
    const float* bk      = (const float*)d_in[6];
    const float* Wv      = (const float*)d_in[7];
    const float* bv      = (const float*)d_in[8];
    const float* Wo      = (const float*)d_in[9];
    const float* bo      = (const float*)d_in[10];
    const int*   idx     = (const int*)d_in[11];
    float* out = (float*)d_out;

    cudaFuncSetAttribute(gemm_mma_kernel,
                         cudaFuncAttributeMaxDynamicSharedMemorySize, SMEM_MMA);

    void *pc2, *pQKs, *pS, *pYp, *pzb;
    void *pqh, *pql, *pkh, *pkl, *pvTh, *pvTl, *pw2h, *pw2l, *pqwh, *pqwl, *pPh, *pPl;
    cudaGetSymbolAddress(&pc2, g_c2);
    cudaGetSymbolAddress(&pQKs, g_QKs);
    cudaGetSymbolAddress(&pS, g_S);
    cudaGetSymbolAddress(&pYp, g_Yp);
    cudaGetSymbolAddress(&pzb, g_zb);
    cudaGetSymbolAddress(&pqh, g_qh);   cudaGetSymbolAddress(&pql, g_ql);
    cudaGetSymbolAddress(&pkh, g_kh);   cudaGetSymbolAddress(&pkl, g_kl);
    cudaGetSymbolAddress(&pvTh, g_vTh); cudaGetSymbolAddress(&pvTl, g_vTl);
    cudaGetSymbolAddress(&pw2h, g_w2h); cudaGetSymbolAddress(&pw2l, g_w2l);
    cudaGetSymbolAddress(&pqwh, g_qwh); cudaGetSymbolAddress(&pqwl, g_qwl);
    cudaGetSymbolAddress(&pPh, g_Ph);   cudaGetSymbolAddress(&pPl, g_Pl);

    reset_mask_kernel<<<(Bq * Lq + 255) / 256, 256>>>();

    // splits: queries, keys (row-major), values (transposed)
    {
        int nBig = Bq * Lq * DM / 4;
        split_kernel<<<(nBig + 255) / 256, 256>>>((const float4*)queries,
            (uint2*)pqh, (uint2*)pql, nBig);
        split_kernel<<<(nBig + 255) / 256, 256>>>((const float4*)keys,
            (uint2*)pkh, (uint2*)pkl, nBig);
        splitT_kernel<<<dim3(DM / 32, Sq / 32, Bq), 256>>>(values,
            (__nv_bfloat16*)pvTh, (__nv_bfloat16*)pvTl);
    }

    // W2 + c2 (K_sample computed in-kernel from keys/Wk/bk)
    build_w2_kernel<<<Bq * NH, 256>>>(keys, Wq, Wk, bq, bk, idx);

    // QKs[b] = queries[b] @ W2[b]^T + c2[b]  (M=4096, N=640, K=1024)
    gemm_mma_kernel<<<dim3(NHT / 128, Lq / 128, Bq), 256, SMEM_MMA>>>(
        (const __nv_bfloat16*)pqh, (const __nv_bfloat16*)pql,
        (const __nv_bfloat16*)pw2h, (const __nv_bfloat16*)pw2l,
        (const float*)pc2, (float*)pQKs,
        NHT, DM, DM / BKg, 1,
        (size_t)Lq * DM, (size_t)NHT * DM, (size_t)NHT, (size_t)Lq * NHT);

    reduce_m_kernel<<<(Bq * Lq * NH) / 8, 256>>>();
    topk_kernel<<<Bq * NH, 256>>>();
    qred_kernel<<<Bq * NH * NT, 256>>>(queries, Wq, bq);
    qw_kernel<<<Bq * NH, 256>>>(Wk);

    // S[b] = QW[b] @ keys[b]^T  (M=640, N=4096, K=1024); bk shift cancels in softmax
    gemm_mma_kernel<<<dim3(Sq / 128, NHT / 128, Bq), 256, SMEM_MMA>>>(
        (const __nv_bfloat16*)pqwh, (const __nv_bfloat16*)pqwl,
        (const __nv_bfloat16*)pkh, (const __nv_bfloat16*)pkl,
        (const float*)pzb, (float*)pS,
        Sq, DM, DM / BKg, 1,
        (size_t)NHT * DM, (size_t)Sq * DM, (size_t)0, (size_t)NHT * Sq);

    softmax_kernel<<<Bq * NHT, 256>>>();

    // Y[b] = P[b] @ values[b]  (M=640, N=1024, K=4096), split-K=2 partials
    gemm_mma_kernel<<<dim3(DM / 128, NHT / 128, Bq * 2), 256, SMEM_MMA>>>(
        (const __nv_bfloat16*)pPh, (const __nv_bfloat16*)pPl,
        (const __nv_bfloat16*)pvTh, (const __nv_bfloat16*)pvTl,
        (const float*)pzb, (float*)pYp,
        DM, Sq, (Sq / 2) / BKg, 2,
        (size_t)NHT * Sq, (size_t)DM * Sq, (size_t)0, (size_t)NHT * DM);

    ctx_kernel<<<Bq * NH * NT, 256>>>(Wv, bv);
    out_kernel<<<Bq * Lq, 256>>>(Wo, bo, out);
}

// round 9
// speedup vs baseline: 2.7720x; 1.2183x over previous
#include <cuda_runtime.h>
#include <cuda_bf16.h>
#include <cstdint>

#define Bq 4
#define Lq 4096
#define Sq 4096
#define DM 1024
#define NH 16
#define DKq 64
#define SK 40
#define NT 40
#define FSCALE 0.125f
#define NHT (NH * NT)
#define KSPL 4                        // split-K for Y GEMM
#define NCHK 16                       // top-k phase A chunks

// GEMM tiling
#define BKg 32
#define ASTR 40
#define TILE_B (128 * ASTR * 2)
#define STAGE_B (4 * TILE_B)
#define SMEM_MMA (2 * STAGE_B)

// ---------------- scratch ----------------------------------------------------
__device__ float    g_c2[Bq*NH*SK];
__device__ float    g_ks[Bq*NH*SK*DKq];
__device__ float    g_QKs[(size_t)Bq*Lq*NHT];
__device__ float    g_Mv[Bq*NH*Lq];
__device__ int      g_Mtop[Bq*NH*NT];
__device__ float    g_cand_v[Bq*NH*NCHK*NT];
__device__ int      g_cand_i[Bq*NH*NCHK*NT];
__device__ float    g_Qred[(size_t)Bq*NH*NT*DKq];
__device__ float    g_ctx[(size_t)Bq*NH*NT*DKq];
__device__ unsigned g_mask[Bq*Lq];
__device__ int      g_tslot[(size_t)Bq*Lq*NH];
__device__ float    g_S[(size_t)Bq*NHT*Sq];
__device__ float    g_Yp[(size_t)KSPL*Bq*NHT*DM];
__device__ float    g_WoT[(size_t)DM*DM];
__device__ float    g_zb[4096];       // stays zero

__device__ __nv_bfloat16 g_qh[(size_t)Bq*Lq*DM],  g_ql[(size_t)Bq*Lq*DM];
__device__ __nv_bfloat16 g_kh[(size_t)Bq*Sq*DM],  g_kl[(size_t)Bq*Sq*DM];
__device__ __nv_bfloat16 g_vTh[(size_t)Bq*DM*Sq], g_vTl[(size_t)Bq*DM*Sq];
__device__ __nv_bfloat16 g_w2h[(size_t)Bq*NH*SK*DM], g_w2l[(size_t)Bq*NH*SK*DM];
__device__ __nv_bfloat16 g_qwh[(size_t)Bq*NHT*DM], g_qwl[(size_t)Bq*NHT*DM];
__device__ __nv_bfloat16 g_Ph[(size_t)Bq*NHT*Sq], g_Pl[(size_t)Bq*NHT*Sq];

// ---------------- helpers ----------------------------------------------------
__device__ __forceinline__ uint32_t smem_u32(const void* p) {
    uint32_t a;
    asm("{ .reg .u64 t; cvta.to.shared.u64 t, %1; cvt.u32.u64 %0, t; }" : "=r"(a) : "l"(p));
    return a;
}
__device__ __forceinline__ void cp16(uint32_t sa, const void* gp) {
    asm volatile("cp.async.cg.shared.global [%0], [%1], 16;" :: "r"(sa), "l"(gp) : "memory");
}
__device__ __forceinline__ uint32_t lds32(uint32_t addr) {
    uint32_t v;
    asm volatile("ld.shared.b32 %0, [%1];" : "=r"(v) : "r"(addr));
    return v;
}
__device__ __forceinline__ void mma_bf16(float* d, const uint32_t* a, const uint32_t* b) {
    asm volatile(
        "mma.sync.aligned.m16n8k16.row.col.f32.bf16.bf16.f32 "
        "{%0,%1,%2,%3}, {%4,%5,%6,%7}, {%8,%9}, {%0,%1,%2,%3};"
        : "+f"(d[0]), "+f"(d[1]), "+f"(d[2]), "+f"(d[3])
        : "r"(a[0]), "r"(a[1]), "r"(a[2]), "r"(a[3]), "r"(b[0]), "r"(b[1]));
}
__device__ __forceinline__ void split2(float v, __nv_bfloat16* hp, __nv_bfloat16* lp) {
    __nv_bfloat16 hb = __float2bfloat16_rn(v);
    *hp = hb;
    *lp = __float2bfloat16_rn(v - __bfloat162float(hb));
}

// ---------------- small kernels ---------------------------------------------
__global__ void reset_mask_kernel() {
    int i = blockIdx.x * 256 + threadIdx.x;
    if (i < Bq * Lq) g_mask[i] = 0u;
}

__global__ __launch_bounds__(256) void split_kernel(
    const float4* __restrict__ x, uint2* __restrict__ hi, uint2* __restrict__ lo, int n4)
{
    int i = blockIdx.x * 256 + threadIdx.x;
    if (i >= n4) return;
    float4 v = x[i];
    float vv[4] = {v.x, v.y, v.z, v.w};
    unsigned h[4], l[4];
#pragma unroll
    for (int j = 0; j < 4; j++) {
        __nv_bfloat16 hb = __float2bfloat16_rn(vv[j]);
        float r = vv[j] - __bfloat162float(hb);
        h[j] = __bfloat16_as_ushort(hb);
        l[j] = __bfloat16_as_ushort(__float2bfloat16_rn(r));
    }
    hi[i] = make_uint2(h[0] | (h[1] << 16), h[2] | (h[3] << 16));
    lo[i] = make_uint2(l[0] | (l[1] << 16), l[2] | (l[3] << 16));
}

__global__ __launch_bounds__(256) void splitT_kernel(
    const float* __restrict__ x, __nv_bfloat16* __restrict__ hiT,
    __nv_bfloat16* __restrict__ loT)
{
    __shared__ float t[32][33];
    int b = blockIdx.z;
    int m0 = blockIdx.x * 32, s0 = blockIdx.y * 32;
    int tx = threadIdx.x & 31, ty = threadIdx.x >> 5;
#pragma unroll
    for (int i = 0; i < 4; i++)
        t[ty + i * 8][tx] = x[((size_t)b * Sq + s0 + ty + i * 8) * DM + m0 + tx];
    __syncthreads();
#pragma unroll
    for (int i = 0; i < 4; i++) {
        float v = t[tx][ty + i * 8];
        size_t o = ((size_t)b * DM + m0 + ty + i * 8) * Sq + s0 + tx;
        __nv_bfloat16 hb = __float2bfloat16_rn(v);
        hiT[o] = hb;
        loT[o] = __float2bfloat16_rn(v - __bfloat162float(hb));
    }
}

// fp32 transpose of Wo: WoT[k][m] = Wo[m][k]
__global__ __launch_bounds__(256) void woT_kernel(const float* __restrict__ Wo) {
    __shared__ float t[32][33];
    int m0 = blockIdx.x * 32, k0 = blockIdx.y * 32;
    int tx = threadIdx.x & 31, ty = threadIdx.x >> 5;
#pragma unroll
    for (int i = 0; i < 4; i++)
        t[ty + i * 8][tx] = Wo[(size_t)(m0 + ty + i * 8) * DM + k0 + tx];
    __syncthreads();
#pragma unroll
    for (int i = 0; i < 4; i++)
        g_WoT[(size_t)(k0 + ty + i * 8) * DM + m0 + tx] = t[tx][ty + i * 8];
}

// ---------------- HMMA split-bf16 GEMM --------------------------------------
__device__ __forceinline__ void load_stage_mma(
    uint32_t sbase, int st,
    const __nv_bfloat16* Ah, const __nv_bfloat16* Al,
    const __nv_bfloat16* Wh, const __nv_bfloat16* Wl, int k0, int ldk, int tid)
{
    uint32_t base = sbase + st * STAGE_B;
    const __nv_bfloat16* srcs[4] = {Ah + k0, Al + k0, Wh + k0, Wl + k0};
#pragma unroll
    for (int t = 0; t < 4; t++) {
        const __nv_bfloat16* g = srcs[t];
        uint32_t tb = base + t * TILE_B;
#pragma unroll
        for (int i = 0; i < 2; i++) {
            int id = tid + i * 256;
            int row = id >> 2, ch = id & 3;
            cp16(tb + row * (ASTR * 2) + ch * 16, g + (size_t)row * ldk + ch * 8);
        }
    }
    asm volatile("cp.async.commit_group;" ::: "memory");
}

__global__ __launch_bounds__(256) void gemm_mma_kernel(
    const __nv_bfloat16* __restrict__ Ah, const __nv_bfloat16* __restrict__ Al,
    const __nv_bfloat16* __restrict__ Wh, const __nv_bfloat16* __restrict__ Wl,
    const float* __restrict__ bias, float* __restrict__ C,
    int ldc, int ldk, int nkt, int ksplit,
    size_t aB, size_t wB, size_t bB, size_t cB)
{
    extern __shared__ __align__(16) char smem[];
    int tid = threadIdx.x, wid = tid >> 5, lane = tid & 31;
    int wm = wid & 3, wn = wid >> 2;
    int qr = lane >> 2, qc = lane & 3;
    int z = blockIdx.z;
    int b = z / ksplit, ch = z % ksplit;

    size_t aoff = (size_t)b * aB + (size_t)blockIdx.y * 128 * ldk + (size_t)ch * nkt * BKg;
    size_t woff = (size_t)b * wB + (size_t)blockIdx.x * 128 * ldk + (size_t)ch * nkt * BKg;
    Ah += aoff; Al += aoff; Wh += woff; Wl += woff;
    const float* bias_p = bias + (size_t)b * bB + blockIdx.x * 128;
    float* Cp = C + (size_t)z * cB + (size_t)blockIdx.y * 128 * ldc + blockIdx.x * 128;

    uint32_t sb = smem_u32(smem);

    float acc[2][8][4];
#pragma unroll
    for (int m = 0; m < 2; m++)
#pragma unroll
        for (int f = 0; f < 8; f++)
#pragma unroll
            for (int i = 0; i < 4; i++) acc[m][f][i] = 0.f;

    load_stage_mma(sb, 0, Ah, Al, Wh, Wl, 0, ldk, tid);
    load_stage_mma(sb, 1, Ah, Al, Wh, Wl, BKg, ldk, tid);

    for (int kt = 0; kt < nkt; kt++) {
        asm volatile("cp.async.wait_group 1;" ::: "memory");
        __syncthreads();

        uint32_t stb = sb + (kt & 1) * STAGE_B;
        uint32_t sAh = stb, sAl = stb + TILE_B;
        uint32_t sWh = stb + 2 * TILE_B, sWl = stb + 3 * TILE_B;

#pragma unroll
        for (int kk = 0; kk < BKg; kk += 16) {
            uint32_t ah[2][4], al[2][4], wh2[8][2], wl2[8][2];
#pragma unroll
            for (int m = 0; m < 2; m++) {
                int r0 = wm * 32 + m * 16 + qr;
                uint32_t o00 = (uint32_t)((r0 * ASTR + kk + qc * 2) * 2);
                uint32_t o10 = o00 + 8 * ASTR * 2;
                ah[m][0] = lds32(sAh + o00);  ah[m][1] = lds32(sAh + o10);
                ah[m][2] = lds32(sAh + o00 + 16); ah[m][3] = lds32(sAh + o10 + 16);
                al[m][0] = lds32(sAl + o00);  al[m][1] = lds32(sAl + o10);
                al[m][2] = lds32(sAl + o00 + 16); al[m][3] = lds32(sAl + o10 + 16);
            }
#pragma unroll
            for (int f = 0; f < 8; f++) {
                int n = wn * 64 + f * 8 + qr;
                uint32_t o = (uint32_t)((n * ASTR + kk + qc * 2) * 2);
                wh2[f][0] = lds32(sWh + o); wh2[f][1] = lds32(sWh + o + 16);
                wl2[f][0] = lds32(sWl + o); wl2[f][1] = lds32(sWl + o + 16);
            }
#pragma unroll
            for (int m = 0; m < 2; m++)
#pragma unroll
                for (int f = 0; f < 8; f++) {
                    mma_bf16(acc[m][f], ah[m], wh2[f]);
                    mma_bf16(acc[m][f], ah[m], wl2[f]);
                    mma_bf16(acc[m][f], al[m], wh2[f]);
                }
        }
        __syncthreads();
        if (kt + 2 < nkt)
            load_stage_mma(sb, kt & 1, Ah, Al, Wh, Wl, (kt + 2) * BKg, ldk, tid);
        else
            asm volatile("cp.async.commit_group;" ::: "memory");
    }

#pragma unroll
    for (int m = 0; m < 2; m++) {
        float* Crow0 = Cp + (size_t)(wm * 32 + m * 16 + qr) * ldc;
        float* Crow1 = Crow0 + 8 * ldc;
#pragma unroll
        for (int f = 0; f < 8; f++) {
            int col = wn * 64 + f * 8 + qc * 2;
            float b0 = bias_p[col], b1 = bias_p[col + 1];
            *(float2*)(Crow0 + col) = make_float2(acc[m][f][0] + b0, acc[m][f][1] + b1);
            *(float2*)(Crow1 + col) = make_float2(acc[m][f][2] + b0, acc[m][f][3] + b1);
        }
    }
}

// ---------------- K_sample + c2 ----------------------------------------------
__global__ __launch_bounds__(256) void ksample_kernel(
    const float* __restrict__ keys, const float* __restrict__ Wk,
    const float* __restrict__ bq, const float* __restrict__ bk,
    const int* __restrict__ idx)
{
    int bh = blockIdx.x;
    int b = bh / NH, h = bh % NH;
    __shared__ float ks[SK * DKq];
    __shared__ float kt[SK][65];
    __shared__ float wt[DKq][65];
    int tid = threadIdx.x, lane = tid & 31, grp = tid >> 5;

    float acc[5][2];
#pragma unroll
    for (int k = 0; k < 5; k++) { acc[k][0] = 0.f; acc[k][1] = 0.f; }
    for (int m0 = 0; m0 < DM; m0 += 64) {
        __syncthreads();
        for (int i = tid; i < SK * 64; i += 256) {
            int s = i >> 6, mm = i & 63;
            kt[s][mm] = keys[((size_t)b * Sq + idx[s]) * DM + m0 + mm];
        }
        for (int i = tid; i < DKq * 64; i += 256) {
            int d = i >> 6, mm = i & 63;
            wt[d][mm] = Wk[(size_t)(h * DKq + d) * DM + m0 + mm];
        }
        __syncthreads();
#pragma unroll 8
        for (int mm = 0; mm < 64; mm++) {
            float w0 = wt[lane][mm], w1 = wt[lane + 32][mm];
#pragma unroll
            for (int k = 0; k < 5; k++) {
                float a = kt[grp + k * 8][mm];
                acc[k][0] += a * w0;
                acc[k][1] += a * w1;
            }
        }
    }
    __syncthreads();
#pragma unroll
    for (int k = 0; k < 5; k++) {
        int s = grp + k * 8;
        float v0 = acc[k][0] + bk[h * DKq + lane];
        float v1 = acc[k][1] + bk[h * DKq + lane + 32];
        ks[s * DKq + lane] = v0;      ks[s * DKq + lane + 32] = v1;
        g_ks[(bh * SK + s) * DKq + lane] = v0;
        g_ks[(bh * SK + s) * DKq + lane + 32] = v1;
    }
    __syncthreads();
    if (tid < SK) {
        float c = 0.f;
#pragma unroll
        for (int d = 0; d < DKq; d++) c += bq[h * DKq + d] * ks[tid * DKq + d];
        g_c2[bh * SK + tid] = c;
    }
}

// ---------------- W2 = Wq_h^T @ K_sample (grid 64 x 4) ----------------------
__global__ __launch_bounds__(256) void w2_kernel(const float* __restrict__ Wq) {
    int bh = blockIdx.x;
    int b = bh / NH, h = bh % NH;
    __shared__ float ks[SK * DKq];
    int tid = threadIdx.x;
    for (int i = tid; i < SK * DKq; i += 256) ks[i] = g_ks[bh * SK * DKq + i];
    __syncthreads();
    int n = blockIdx.y * 256 + tid;
    for (int sb = 0; sb < 5; sb++) {
        float a2[8];
#pragma unroll
        for (int s8 = 0; s8 < 8; s8++) a2[s8] = 0.f;
        for (int d = 0; d < DKq; d++) {
            float w = Wq[(size_t)(h * DKq + d) * DM + n];
#pragma unroll
            for (int s8 = 0; s8 < 8; s8++) a2[s8] += w * ks[(sb * 8 + s8) * DKq + d];
        }
#pragma unroll
        for (int s8 = 0; s8 < 8; s8++) {
            size_t o = ((size_t)b * NH * SK + h * SK + sb * 8 + s8) * DM + n;
            split2(a2[s8], &g_w2h[o], &g_w2l[o]);
        }
    }
}

// ---------------- M = max - mean --------------------------------------------
__global__ __launch_bounds__(256) void reduce_m_kernel() {
    int wg = blockIdx.x * 8 + (threadIdx.x >> 5);
    int lane = threadIdx.x & 31;
    int h = wg % NH;
    int bl = wg / NH;
    int b = bl / Lq, l = bl % Lq;
    const float* p = g_QKs + (size_t)bl * NHT + h * SK;
    float v0 = p[lane];
    float v1 = (lane < SK - 32) ? p[32 + lane] : -3.0e38f;
    float mx = fmaxf(v0, v1);
    float sm = v0 + ((lane < SK - 32) ? p[32 + lane] : 0.f);
#pragma unroll
    for (int o = 16; o; o >>= 1) {
        mx = fmaxf(mx, __shfl_xor_sync(~0u, mx, o));
        sm += __shfl_xor_sync(~0u, sm, o);
    }
    if (lane == 0)
        g_Mv[((size_t)b * NH + h) * Lq + l] = mx - sm * (1.0f / SK);
}

// ---------------- top-40 phase A: per-256-chunk candidates ------------------
__global__ __launch_bounds__(256) void topkA_kernel() {
    int bh = blockIdx.x, c = blockIdx.y;
    int tid = threadIdx.x, lane = tid & 31, warp = tid >> 5;
    float v = g_Mv[(size_t)bh * Lq + c * 256 + tid];
    int myidx = c * 256 + tid;
    __shared__ float wv[8];
    __shared__ int   wi[8];
    __shared__ float bestv;
    __shared__ int   besti;
    for (int t = 0; t < NT; t++) {
        float mv = v; int mi = myidx;
#pragma unroll
        for (int o = 16; o; o >>= 1) {
            float ov = __shfl_xor_sync(~0u, mv, o);
            int   oi = __shfl_xor_sync(~0u, mi, o);
            if (ov > mv || (ov == mv && oi < mi)) { mv = ov; mi = oi; }
        }
        if (lane == 0) { wv[warp] = mv; wi[warp] = mi; }
        __syncthreads();
        if (warp == 0) {
            float m2 = (lane < 8) ? wv[lane] : -3.4e38f;
            int   i2 = (lane < 8) ? wi[lane] : 0x7fffffff;
#pragma unroll
            for (int o = 4; o; o >>= 1) {
                float ov = __shfl_xor_sync(~0u, m2, o);
                int   oi = __shfl_xor_sync(~0u, i2, o);
                if (ov > m2 || (ov == m2 && oi < i2)) { m2 = ov; i2 = oi; }
            }
            if (lane == 0) { bestv = m2; besti = i2; }
        }
        __syncthreads();
        if (myidx == besti) v = -3.4e38f;
        if (tid == 0) {
            g_cand_v[(bh * NCHK + c) * NT + t] = bestv;
            g_cand_i[(bh * NCHK + c) * NT + t] = besti;
        }
        __syncthreads();
    }
}

// ---------------- top-40 phase B: merge 640 candidates ----------------------
__global__ __launch_bounds__(256) void topkB_kernel() {
    int bh = blockIdx.x;
    int b = bh / NH, h = bh % NH;
    int tid = threadIdx.x, lane = tid & 31, warp = tid >> 5;
    float v[3]; int ix[3];
#pragma unroll
    for (int j = 0; j < 3; j++) {
        int s = tid + j * 256;
        if (s < NCHK * NT) {
            v[j]  = g_cand_v[bh * NCHK * NT + s];
            ix[j] = g_cand_i[bh * NCHK * NT + s];
        } else { v[j] = -3.4e38f; ix[j] = 0x7fffffff; }
    }
    __shared__ float wv[8];
    __shared__ int   wi[8];
    __shared__ float bestv;
    __shared__ int   besti;
    for (int t = 0; t < NT; t++) {
        float mv = v[0]; int mi = ix[0];
#pragma unroll
        for (int j = 1; j < 3; j++)
            if (v[j] > mv || (v[j] == mv && ix[j] < mi)) { mv = v[j]; mi = ix[j]; }
#pragma unroll
        for (int o = 16; o; o >>= 1) {
            float ov = __shfl_xor_sync(~0u, mv, o);
            int   oi = __shfl_xor_sync(~0u, mi, o);
            if (ov > mv || (ov == mv && oi < mi)) { mv = ov; mi = oi; }
        }
        if (lane == 0) { wv[warp] = mv; wi[warp] = mi; }
        __syncthreads();
        if (warp == 0) {
            float m2 = (lane < 8) ? wv[lane] : -3.4e38f;
            int   i2 = (lane < 8) ? wi[lane] : 0x7fffffff;
#pragma unroll
            for (int o = 4; o; o >>= 1) {
                float ov = __shfl_xor_sync(~0u, m2, o);
                int   oi = __shfl_xor_sync(~0u, i2, o);
                if (ov > m2 || (ov == m2 && oi < i2)) { m2 = ov; i2 = oi; }
            }
            if (lane == 0) { bestv = m2; besti = i2; }
        }
        __syncthreads();
#pragma unroll
        for (int j = 0; j < 3; j++)
            if (ix[j] == besti) v[j] = -3.4e38f;
        if (tid == 0) {
            int li = besti;
            g_Mtop[bh * NT + t] = li;
            g_tslot[((size_t)b * Lq + li) * NH + h] = t;
            atomicOr(&g_mask[b * Lq + li], 1u << h);
        }
        __syncthreads();
    }
}

// ---------------- Q_red (exact fp32) ----------------------------------------
__global__ __launch_bounds__(256) void qred_kernel(
    const float* __restrict__ queries, const float* __restrict__ Wq,
    const float* __restrict__ bq)
{
    int gb = blockIdx.x;
    int t = gb % NT; int bh = gb / NT;
    int h = bh % NH; int b = bh / NH;
    int l = g_Mtop[bh * NT + t];
    __shared__ float qrow[DM];
    int tid = threadIdx.x;
    ((float4*)qrow)[tid] = ((const float4*)(queries + ((size_t)b * Lq + l) * DM))[tid];
    __syncthreads();
    int warp = tid >> 5, lane = tid & 31;
#pragma unroll
    for (int p = 0; p < 8; p++) {
        int d = p * 8 + warp;
        const float* wrow = Wq + (size_t)(h * DKq + d) * DM;
        float s = 0.f;
#pragma unroll
        for (int it = 0; it < 8; it++) {
            float4 w4 = *(const float4*)(wrow + it * 128 + lane * 4);
            float4 q4 = *(const float4*)(qrow + it * 128 + lane * 4);
            s += w4.x * q4.x + w4.y * q4.y + w4.z * q4.z + w4.w * q4.w;
        }
#pragma unroll
        for (int o = 16; o; o >>= 1) s += __shfl_xor_sync(~0u, s, o);
        if (lane == 0) g_Qred[(size_t)gb * DKq + d] = s + bq[h * DKq + d];
    }
}

// ---------------- QW = Qred @ Wk_h  (grid 64 x 4) ---------------------------
__global__ __launch_bounds__(256) void qw_kernel(const float* __restrict__ Wk) {
    int bh = blockIdx.x;
    int h = bh % NH;
    __shared__ float qs[NT * DKq];
    int tid = threadIdx.x;
    for (int i = tid; i < NT * DKq; i += 256)
        qs[i] = g_Qred[(size_t)bh * NT * DKq + i];
    __syncthreads();
    int n = blockIdx.y * 256 + tid;
    for (int sb = 0; sb < 5; sb++) {
        float a2[8];
#pragma unroll
        for (int t8 = 0; t8 < 8; t8++) a2[t8] = 0.f;
        for (int d = 0; d < DKq; d++) {
            float w = Wk[(size_t)(h * DKq + d) * DM + n];
#pragma unroll
            for (int t8 = 0; t8 < 8; t8++) a2[t8] += w * qs[(sb * 8 + t8) * DKq + d];
        }
#pragma unroll
        for (int t8 = 0; t8 < 8; t8++) {
            size_t o = ((size_t)bh * NT + sb * 8 + t8) * DM + n;
            split2(a2[t8], &g_qwh[o], &g_qwl[o]);
        }
    }
}

// ---------------- softmax over S rows -> P hi/lo ----------------------------
__global__ __launch_bounds__(256) void softmax_kernel() {
    int r = blockIdx.x;
    const float* Sp = g_S + (size_t)r * Sq;
    int tid = threadIdx.x;
    float v[16];
    float mx = -3.0e38f;
#pragma unroll
    for (int i = 0; i < 16; i++) {
        v[i] = Sp[tid + i * 256] * FSCALE;
        mx = fmaxf(mx, v[i]);
    }
    __shared__ float red[256];
    red[tid] = mx; __syncthreads();
    for (int s = 128; s; s >>= 1) {
        if (tid < s) red[tid] = fmaxf(red[tid], red[tid + s]);
        __syncthreads();
    }
    mx = red[0]; __syncthreads();
    float sm = 0.f;
#pragma unroll
    for (int i = 0; i < 16; i++) { v[i] = expf(v[i] - mx); sm += v[i]; }
    red[tid] = sm; __syncthreads();
    for (int s = 128; s; s >>= 1) {
        if (tid < s) red[tid] += red[tid + s];
        __syncthreads();
    }
    float inv = 1.0f / red[0];
#pragma unroll
    for (int i = 0; i < 16; i++) {
        float p = v[i] * inv;
        size_t o = (size_t)r * Sq + tid + i * 256;
        __nv_bfloat16 hb = __float2bfloat16_rn(p);
        g_Ph[o] = hb;
        g_Pl[o] = __float2bfloat16_rn(p - __bfloat162float(hb));
    }
}

// ---------------- ctx = sum(Yp) @ Wv_h^T + bv -------------------------------
__global__ __launch_bounds__(256) void ctx_kernel(
    const float* __restrict__ Wv, const float* __restrict__ bv)
{
    int gb = blockIdx.x;
    int t = gb % NT; int bh = gb / NT;
    int h = bh % NH; int b = bh / NH;
    int ht = h * NT + t;
    __shared__ float y[DM];
    int tid = threadIdx.x;
    float4 s4 = make_float4(0.f, 0.f, 0.f, 0.f);
#pragma unroll
    for (int c = 0; c < KSPL; c++) {
        float4 a = ((const float4*)(g_Yp + ((size_t)(b * KSPL + c) * NHT + ht) * DM))[tid];
        s4.x += a.x; s4.y += a.y; s4.z += a.z; s4.w += a.w;
    }
    ((float4*)y)[tid] = s4;
    __syncthreads();
    int warp = tid >> 5, lane = tid & 31;
#pragma unroll
    for (int p = 0; p < 8; p++) {
        int d = p * 8 + warp;
        const float* wrow = Wv + (size_t)(h * DKq + d) * DM;
        float s = 0.f;
#pragma unroll
        for (int it = 0; it < 8; it++) {
            float4 w4 = *(const float4*)(wrow + it * 128 + lane * 4);
            float4 q4 = *(const float4*)(y + it * 128 + lane * 4);
            s += w4.x * q4.x + w4.y * q4.y + w4.z * q4.z + w4.w * q4.w;
        }
#pragma unroll
        for (int o = 16; o; o >>= 1) s += __shfl_xor_sync(~0u, s, o);
        if (lane == 0) g_ctx[(size_t)gb * DKq + d] = s + bv[h * DKq + d];
    }
}

// ---------------- sparse output projection (WoT, coalesced) -----------------
__global__ __launch_bounds__(256) void out_kernel(
    const float* __restrict__ bo, float* __restrict__ out)
{
    int row = blockIdx.x;
    int b = row / Lq;
    int tid = threadIdx.x;
    unsigned msk = g_mask[row];
    __shared__ float csm[DKq];

    float4 a4 = ((const float4*)bo)[tid];

    if (msk) {
        for (int h = 0; h < NH; h++) {
            if (!((msk >> h) & 1u)) continue;
            int t = g_tslot[(size_t)row * NH + h];
            __syncthreads();
            if (tid < DKq / 4)
                ((float4*)csm)[tid] =
                    ((const float4*)(g_ctx + ((size_t)(b * NH + h) * NT + t) * DKq))[tid];
            __syncthreads();
#pragma unroll 8
            for (int d = 0; d < DKq; d++) {
                float c = csm[d];
                float4 w4 = ((const float4*)(g_WoT + (size_t)(h * DKq + d) * DM))[tid];
                a4.x += c * w4.x; a4.y += c * w4.y;
                a4.z += c * w4.z; a4.w += c * w4.w;
            }
        }
    }
    ((float4*)(out + (size_t)row * DM))[tid] = a4;
}

// ---------------- launch -----------------------------------------------------
extern "C" void kernel_launch(void* const* d_in, const int* in_sizes, int n_in,
                              void* d_out, int out_size)
{
    const float* queries = (const float*)d_in[0];
    const float* keys    = (const float*)d_in[1];
    const float* values  = (const float*)d_in[2];
    const float* Wq      = (const float*)d_in[3];
    const float* bq      = (const float*)d_in[4];
    const float* Wk      = (const float*)d_in[5];
    const float* bk      = (const float*)d_in[6];
    const float* Wv      = (const float*)d_in[7];
    const float* bv      = (const float*)d_in[8];
    const float* Wo      = (const float*)d_in[9];
    const float* bo      = (const float*)d_in[10];
    const int*   idx     = (const int*)d_in[11];
    float* out = (float*)d_out;

    cudaFuncSetAttribute(gemm_mma_kernel,
                         cudaFuncAttributeMaxDynamicSharedMemorySize, SMEM_MMA);

    void *pc2, *pQKs, *pS, *pYp, *pzb;
    void *pqh, *pql, *pkh, *pkl, *pvTh, *pvTl, *pw2h, *pw2l, *pqwh, *pqwl, *pPh, *pPl;
    cudaGetSymbolAddress(&pc2, g_c2);
    cudaGetSymbolAddress(&pQKs, g_QKs);
    cudaGetSymbolAddress(&pS, g_S);
    cudaGetSymbolAddress(&pYp, g_Yp);
    cudaGetSymbolAddress(&pzb, g_zb);
    cudaGetSymbolAddress(&pqh, g_qh);   cudaGetSymbolAddress(&pql, g_ql);
    cudaGetSymbolAddress(&pkh, g_kh);   cudaGetSymbolAddress(&pkl, g_kl);
    cudaGetSymbolAddress(&pvTh, g_vTh); cudaGetSymbolAddress(&pvTl, g_vTl);
    cudaGetSymbolAddress(&pw2h, g_w2h); cudaGetSymbolAddress(&pw2l, g_w2l);
    cudaGetSymbolAddress(&pqwh, g_qwh); cudaGetSymbolAddress(&pqwl, g_qwl);
    cudaGetSymbolAddress(&pPh, g_Ph);   cudaGetSymbolAddress(&pPl, g_Pl);

    reset_mask_kernel<<<(Bq * Lq + 255) / 256, 256>>>();
    woT_kernel<<<dim3(DM / 32, DM / 32), 256>>>(Wo);

    {
        int nBig = Bq * Lq * DM / 4;
        split_kernel<<<(nBig + 255) / 256, 256>>>((const float4*)queries,
            (uint2*)pqh, (uint2*)pql, nBig);
        split_kernel<<<(nBig + 255) / 256, 256>>>((const float4*)keys,
            (uint2*)pkh, (uint2*)pkl, nBig);
        splitT_kernel<<<dim3(DM / 32, Sq / 32, Bq), 256>>>(values,
            (__nv_bfloat16*)pvTh, (__nv_bfloat16*)pvTl);
    }

    ksample_kernel<<<Bq * NH, 256>>>(keys, Wk, bq, bk, idx);
    w2_kernel<<<dim3(Bq * NH, 4), 256>>>(Wq);

    // QKs[b] = queries[b] @ W2[b]^T + c2[b]
    gemm_mma_kernel<<<dim3(NHT / 128, Lq / 128, Bq), 256, SMEM_MMA>>>(
        (const __nv_bfloat16*)pqh, (const __nv_bfloat16*)pql,
        (const __nv_bfloat16*)pw2h, (const __nv_bfloat16*)pw2l,
        (const float*)pc2, (float*)pQKs,
        NHT, DM, DM / BKg, 1,
        (size_t)Lq * DM, (size_t)NHT * DM, (size_t)NHT, (size_t)Lq * NHT);

    reduce_m_kernel<<<(Bq * Lq * NH) / 8, 256>>>();
    topkA_kernel<<<dim3(Bq * NH, NCHK), 256>>>();
    topkB_kernel<<<Bq * NH, 256>>>();
    qred_kernel<<<Bq * NH * NT, 256>>>(queries, Wq, bq);
    qw_kernel<<<dim3(Bq * NH, 4), 256>>>(Wk);

    // S[b] = QW[b] @ keys[b]^T
    gemm_mma_kernel<<<dim3(Sq / 128, NHT / 128, Bq), 256, SMEM_MMA>>>(
        (const __nv_bfloat16*)pqwh, (const __nv_bfloat16*)pqwl,
        (const __nv_bfloat16*)pkh, (const __nv_bfloat16*)pkl,
        (const float*)pzb, (float*)pS,
        Sq, DM, DM / BKg, 1,
        (size_t)NHT * DM, (size_t)Sq * DM, (size_t)0, (size_t)NHT * Sq);

    softmax_kernel<<<Bq * NHT, 256>>>();

    // Y[b] = P[b] @ values[b], split-K=4
    gemm_mma_kernel<<<dim3(DM / 128, NHT / 128, Bq * KSPL), 256, SMEM_MMA>>>(
        (const __nv_bfloat16*)pPh, (const __nv_bfloat16*)pPl,
        (const __nv_bfloat16*)pvTh, (const __nv_bfloat16*)pvTl,
        (const float*)pzb, (float*)pYp,
        DM, Sq, (Sq / KSPL) / BKg, KSPL,
        (size_t)NHT * Sq, (size_t)DM * Sq, (size_t)0, (size_t)NHT * DM);

    ctx_kernel<<<Bq * NH * NT, 256>>>(Wv, bv);
    out_kernel<<<Bq * Lq, 256>>>(bo, out);
}